// round 16
// baseline (speedup 1.0000x reference)
#include <cuda_runtime.h>
#include <cuda_fp16.h>
#include <cstdint>
#include <math.h>

// Problem constants
#define NTOK  65536
#define EFULL 512
#define HIDC  256
#define NGR   4096
#define GSZ   16
#define KPAD1 544          // 514 padded to %32

// ---------------- scratch (__device__ globals) ----------------
__device__ __half g_h1h[(size_t)NTOK * HIDC];
__device__ __half g_h1l[(size_t)NTOK * HIDC];
__device__ __half g_h2h[(size_t)NTOK * HIDC];
__device__ __half g_h2l[(size_t)NTOK * HIDC];
__device__ __half g_qk[(size_t)NTOK * 1024];
__device__ __half g_xwh[(size_t)2 * NGR * HIDC];
__device__ __half g_xwl[(size_t)2 * NGR * HIDC];
__device__ __half g_omh[(size_t)NGR * EFULL];
__device__ __half g_oml[(size_t)NGR * EFULL];
__device__ __half g_kmh[(size_t)NGR * EFULL];
__device__ __half g_kml[(size_t)NGR * EFULL];
__device__ float  g_kmp[(size_t)NGR * HIDC];
__device__ __half g_hgah[(size_t)NGR * HIDC];
__device__ __half g_hgal[(size_t)NGR * HIDC];
__device__ __half g_hgbh[(size_t)NGR * HIDC];
__device__ __half g_hgbl[(size_t)NGR * HIDC];
__device__ float  g_bc[1024];
__device__ float  g_bv2[512];
__device__ float  g_bb[256];

// weight pool (single fp16). offsets in elements:
#define OW_P1W1 0                 // 256x544
#define OW_P1W2 139264            // 256x256
#define OW_P1W3 204800            // 256x256
#define OW_WOUT 270336            // 512x512
#define OW_GW1  532480            // 256x512
#define OW_GW2  663552            // 256x256
#define OW_GW3  729088            // 256x256
#define OW_P2W1 794624            // 256x512
#define OW_P2W2 925696            // 256x256
#define OW_WC   991232            // Wqk@W4: 1024x256
#define OW_WVC  1253376           // Wv01@W4: 512x256
#define OW_WC3  1384448           // -(P2W1@W4)/16: 256x256
#define OW_TOT  1449984
__device__ __half g_wp[OW_TOT];

__device__ __forceinline__ float elu1(float x) {
    return x > 0.f ? x : (expf(x) - 1.f);
}
__device__ __forceinline__ uint32_t smem_u32(const void* p) {
    uint32_t a;
    asm("{ .reg .u64 t; cvta.to.shared.u64 t, %1; cvt.u32.u64 %0, t; }" : "=r"(a) : "l"(p));
    return a;
}
__device__ __forceinline__ void ldsm4(uint32_t& r0, uint32_t& r1, uint32_t& r2, uint32_t& r3,
                                      uint32_t addr) {
    asm volatile("ldmatrix.sync.aligned.m8n8.x4.shared.b16 {%0,%1,%2,%3}, [%4];"
                 : "=r"(r0), "=r"(r1), "=r"(r2), "=r"(r3) : "r"(addr));
}
__device__ __forceinline__ void mma16816(float* c, const uint32_t* a, const uint32_t* b) {
    asm volatile("mma.sync.aligned.m16n8k16.row.col.f32.f16.f16.f32 "
                 "{%0,%1,%2,%3}, {%4,%5,%6,%7}, {%8,%9}, {%0,%1,%2,%3};"
                 : "+f"(c[0]), "+f"(c[1]), "+f"(c[2]), "+f"(c[3])
                 : "r"(a[0]), "r"(a[1]), "r"(a[2]), "r"(a[3]), "r"(b[0]), "r"(b[1]));
}
__device__ __forceinline__ void cvt_split2(float a, float b, uint32_t& hi, uint32_t& lo) {
    __half2 h = __floats2half2_rn(a, b);
    float2 hf = __half22float2(h);
    __half2 l = __floats2half2_rn(a - hf.x, b - hf.y);
    hi = *reinterpret_cast<uint32_t*>(&h);
    lo = *reinterpret_cast<uint32_t*>(&l);
}
__device__ __forceinline__ float2 h2f2(uint32_t u) {
    return __half22float2(*reinterpret_cast<__half2*>(&u));
}
__device__ __forceinline__ uint32_t swz(uint32_t x) { return x ^ ((x >> 3) & 0x70); }

#define CP16(dst, src) \
    asm volatile("cp.async.cg.shared.global [%0], [%1], 16;" :: "r"(dst), "l"(src))
#define CP_COMMIT() asm volatile("cp.async.commit_group;" ::: "memory")
#define CP_WAIT1()  asm volatile("cp.async.wait_group 1;" ::: "memory")
#define CP_WAIT0()  asm volatile("cp.async.wait_group 0;" ::: "memory")

// ======== 2-pass fp16 NT GEMM: A split hi/lo (exact), B single fp16 ==========
#define STAGE 24576
#define SMEM_TOT (3 * STAGE)

template <int EPI, bool WF32, bool WSPLIT>
__global__ __launch_bounds__(256, 2) void gemm_2p(
    const __half* __restrict__ Ah, const __half* __restrict__ Al,
    const __half* __restrict__ B,
    const float* __restrict__ bias, float* __restrict__ C,
    __half* __restrict__ Ch, __half* __restrict__ Cl,
    int K, int ldC)
{
    extern __shared__ __align__(1024) char smem[];
    const uint32_t sb = smem_u32(smem);
    const int tid = threadIdx.x;
    const int lane = tid & 31;
    const int wid = tid >> 5;
    const int wm = wid & 3;
    const int wn = wid >> 2;
    const int m0 = blockIdx.y * 128;
    const int n0 = blockIdx.x * 128;

    const int nch = K >> 5;
    float acc[2][8][4] = {};
    const int lr = (tid >> 2);
    const int lc = tid & 3;

    auto issue = [&](int ci, int stg) {
        const int k0 = ci << 5;
        const uint32_t so = sb + stg * STAGE;
#pragma unroll
        for (int j = 0; j < 2; j++) {
            int r = lr + j * 64;
            uint32_t d = swz((uint32_t)(r * 64 + lc * 16));
            size_t ao = (size_t)(m0 + r) * K + k0 + lc * 8;
            size_t bo = (size_t)(n0 + r) * K + k0 + lc * 8;
            CP16(so + d,         Ah + ao);
            CP16(so + 8192 + d,  Al + ao);
            CP16(so + 16384 + d, B + bo);
        }
        CP_COMMIT();
    };

    issue(0, 0);
    if (nch > 1) issue(1, 1);

    int stg = 0;
    for (int ci = 0; ci < nch; ci++) {
        if (ci + 1 < nch) { CP_WAIT1(); } else { CP_WAIT0(); }
        __syncthreads();
        if (ci + 2 < nch) {
            int ns = stg + 2; if (ns >= 3) ns -= 3;
            issue(ci + 2, ns);
        }
        const uint32_t so = sb + stg * STAGE;
#pragma unroll
        for (int kk = 0; kk < 2; kk++) {
            uint32_t ah[2][4], al_[2][4];
            {
                int ar = lane & 15;
                int akb = kk * 32 + ((lane >> 4) * 16);
#pragma unroll
                for (int i = 0; i < 2; i++) {
                    uint32_t off = swz((uint32_t)((wm * 32 + i * 16 + ar) * 64 + akb));
                    ldsm4(ah[i][0], ah[i][1], ah[i][2], ah[i][3], so + off);
                    ldsm4(al_[i][0], al_[i][1], al_[i][2], al_[i][3], so + 8192 + off);
                }
            }
            uint32_t bh[8][2];
            {
                int br = (lane & 7) + ((lane >> 4) & 1) * 8;
                int bkb = ((lane >> 3) & 1) * 16 + kk * 32;
#pragma unroll
                for (int jf = 0; jf < 4; jf++) {
                    uint32_t off = swz((uint32_t)((wn * 64 + jf * 16 + br) * 64 + bkb));
                    uint32_t r0, r1, r2, r3;
                    ldsm4(r0, r1, r2, r3, so + 16384 + off);
                    bh[2 * jf][0] = r0; bh[2 * jf][1] = r1;
                    bh[2 * jf + 1][0] = r2; bh[2 * jf + 1][1] = r3;
                }
            }
#pragma unroll
            for (int i = 0; i < 2; i++)
#pragma unroll
                for (int j = 0; j < 8; j++)
                    mma16816(acc[i][j], ah[i], bh[j]);
#pragma unroll
            for (int i = 0; i < 2; i++)
#pragma unroll
                for (int j = 0; j < 8; j++)
                    mma16816(acc[i][j], al_[i], bh[j]);
        }
        stg++; if (stg == 3) stg = 0;
    }

#pragma unroll
    for (int i = 0; i < 2; i++) {
        int row = m0 + wm * 32 + i * 16 + (lane >> 2);
#pragma unroll
        for (int j = 0; j < 8; j++) {
            int col = n0 + wn * 64 + j * 8 + (lane & 3) * 2;
            float b0 = bias[col], b1 = bias[col + 1];
            float v0 = acc[i][j][0] + b0, v1 = acc[i][j][1] + b1;
            float v2 = acc[i][j][2] + b0, v3 = acc[i][j][3] + b1;
            if (EPI >= 1) { v0 = elu1(v0); v1 = elu1(v1); v2 = elu1(v2); v3 = elu1(v3); }
            if (EPI == 2) { v0 = elu1(v0); v1 = elu1(v1); v2 = elu1(v2); v3 = elu1(v3); }
            size_t o0 = (size_t)row * ldC + col;
            size_t o1 = (size_t)(row + 8) * ldC + col;
            if (WF32) {
                *reinterpret_cast<float2*>(C + o0) = make_float2(v0, v1);
                *reinterpret_cast<float2*>(C + o1) = make_float2(v2, v3);
            }
            if (WSPLIT) {
                uint32_t hi, lo;
                cvt_split2(v0, v1, hi, lo);
                *reinterpret_cast<uint32_t*>(Ch + o0) = hi;
                *reinterpret_cast<uint32_t*>(Cl + o0) = lo;
                cvt_split2(v2, v3, hi, lo);
                *reinterpret_cast<uint32_t*>(Ch + o1) = hi;
                *reinterpret_cast<uint32_t*>(Cl + o1) = lo;
            }
        }
    }
}

// ======== head-fused o_mean GEMM: per-block A/B select by n0 =================
__global__ __launch_bounds__(256, 2) void gemm_2p_h2(
    const __half* __restrict__ A0h, const __half* __restrict__ A0l,
    const __half* __restrict__ A1h, const __half* __restrict__ A1l,
    const __half* __restrict__ B0, const __half* __restrict__ B1,
    const float* __restrict__ bias,
    __half* __restrict__ Ch, __half* __restrict__ Cl)
{
    extern __shared__ __align__(1024) char smem[];
    const uint32_t sb = smem_u32(smem);
    const int tid = threadIdx.x;
    const int lane = tid & 31;
    const int wid = tid >> 5;
    const int wm = wid & 3;
    const int wn = wid >> 2;
    const int m0 = blockIdx.y * 128;
    const int n0 = blockIdx.x * 128;
    const int K = 256, ldC = 512;
    const bool h1sel = (n0 >= 256);
    const __half* Ah = h1sel ? A1h : A0h;
    const __half* Al = h1sel ? A1l : A0l;
    const __half* B  = h1sel ? B1 : B0;
    const int nb = n0 & 255;

    const int nch = K >> 5;
    float acc[2][8][4] = {};
    const int lr = (tid >> 2);
    const int lc = tid & 3;

    auto issue = [&](int ci, int stg) {
        const int k0 = ci << 5;
        const uint32_t so = sb + stg * STAGE;
#pragma unroll
        for (int j = 0; j < 2; j++) {
            int r = lr + j * 64;
            uint32_t d = swz((uint32_t)(r * 64 + lc * 16));
            size_t ao = (size_t)(m0 + r) * K + k0 + lc * 8;
            size_t bo = (size_t)(nb + r) * K + k0 + lc * 8;
            CP16(so + d,         Ah + ao);
            CP16(so + 8192 + d,  Al + ao);
            CP16(so + 16384 + d, B + bo);
        }
        CP_COMMIT();
    };

    issue(0, 0);
    issue(1, 1);

    int stg = 0;
    for (int ci = 0; ci < nch; ci++) {
        if (ci + 1 < nch) { CP_WAIT1(); } else { CP_WAIT0(); }
        __syncthreads();
        if (ci + 2 < nch) {
            int ns = stg + 2; if (ns >= 3) ns -= 3;
            issue(ci + 2, ns);
        }
        const uint32_t so = sb + stg * STAGE;
#pragma unroll
        for (int kk = 0; kk < 2; kk++) {
            uint32_t ah[2][4], al_[2][4];
            {
                int ar = lane & 15;
                int akb = kk * 32 + ((lane >> 4) * 16);
#pragma unroll
                for (int i = 0; i < 2; i++) {
                    uint32_t off = swz((uint32_t)((wm * 32 + i * 16 + ar) * 64 + akb));
                    ldsm4(ah[i][0], ah[i][1], ah[i][2], ah[i][3], so + off);
                    ldsm4(al_[i][0], al_[i][1], al_[i][2], al_[i][3], so + 8192 + off);
                }
            }
            uint32_t bh[8][2];
            {
                int br = (lane & 7) + ((lane >> 4) & 1) * 8;
                int bkb = ((lane >> 3) & 1) * 16 + kk * 32;
#pragma unroll
                for (int jf = 0; jf < 4; jf++) {
                    uint32_t off = swz((uint32_t)((wn * 64 + jf * 16 + br) * 64 + bkb));
                    uint32_t r0, r1, r2, r3;
                    ldsm4(r0, r1, r2, r3, so + 16384 + off);
                    bh[2 * jf][0] = r0; bh[2 * jf][1] = r1;
                    bh[2 * jf + 1][0] = r2; bh[2 * jf + 1][1] = r3;
                }
            }
#pragma unroll
            for (int i = 0; i < 2; i++)
#pragma unroll
                for (int j = 0; j < 8; j++)
                    mma16816(acc[i][j], ah[i], bh[j]);
#pragma unroll
            for (int i = 0; i < 2; i++)
#pragma unroll
                for (int j = 0; j < 8; j++)
                    mma16816(acc[i][j], al_[i], bh[j]);
        }
        stg++; if (stg == 3) stg = 0;
    }

#pragma unroll
    for (int i = 0; i < 2; i++) {
        int row = m0 + wm * 32 + i * 16 + (lane >> 2);
#pragma unroll
        for (int j = 0; j < 8; j++) {
            int col = n0 + wn * 64 + j * 8 + (lane & 3) * 2;
            float b0 = bias[col], b1 = bias[col + 1];
            float v0 = acc[i][j][0] + b0, v1 = acc[i][j][1] + b1;
            float v2 = acc[i][j][2] + b0, v3 = acc[i][j][3] + b1;
            size_t o0 = (size_t)row * ldC + col;
            size_t o1 = (size_t)(row + 8) * ldC + col;
            uint32_t hi, lo;
            cvt_split2(v0, v1, hi, lo);
            *reinterpret_cast<uint32_t*>(Ch + o0) = hi;
            *reinterpret_cast<uint32_t*>(Cl + o0) = lo;
            cvt_split2(v2, v3, hi, lo);
            *reinterpret_cast<uint32_t*>(Ch + o1) = hi;
            *reinterpret_cast<uint32_t*>(Cl + o1) = lo;
        }
    }
}

// ======== GEMM + fused final-dot epilogue (TWOP selects A-split passes) ======
template <int NOUT, bool TWOP>
__global__ __launch_bounds__(256, 2) void gemm_dot(
    const __half* __restrict__ Ah, const __half* __restrict__ Al,
    const __half* __restrict__ B,
    const float* __restrict__ bias, const float* __restrict__ dw,
    const float* __restrict__ dbias, float* __restrict__ dout, int K)
{
    extern __shared__ __align__(1024) char smem[];
    const uint32_t sb = smem_u32(smem);
    const int tid = threadIdx.x;
    const int lane = tid & 31;
    const int wid = tid >> 5;
    const int wm = wid & 3;
    const int wn = wid >> 2;
    const int m0 = blockIdx.y * 128;
    const int n0 = blockIdx.x * 128;

    const int nch = K >> 5;
    float acc[2][8][4] = {};
    const int lr = (tid >> 2);
    const int lc = tid & 3;

    auto issue = [&](int ci, int stg) {
        const int k0 = ci << 5;
        const uint32_t so = sb + stg * STAGE;
#pragma unroll
        for (int j = 0; j < 2; j++) {
            int r = lr + j * 64;
            uint32_t d = swz((uint32_t)(r * 64 + lc * 16));
            size_t ao = (size_t)(m0 + r) * K + k0 + lc * 8;
            size_t bo = (size_t)(n0 + r) * K + k0 + lc * 8;
            CP16(so + d, Ah + ao);
            if (TWOP) CP16(so + 8192 + d, Al + ao);
            CP16(so + 16384 + d, B + bo);
        }
        CP_COMMIT();
    };

    issue(0, 0);
    if (nch > 1) issue(1, 1);

    int stg = 0;
    for (int ci = 0; ci < nch; ci++) {
        if (ci + 1 < nch) { CP_WAIT1(); } else { CP_WAIT0(); }
        __syncthreads();
        if (ci + 2 < nch) {
            int ns = stg + 2; if (ns >= 3) ns -= 3;
            issue(ci + 2, ns);
        }
        const uint32_t so = sb + stg * STAGE;
#pragma unroll
        for (int kk = 0; kk < 2; kk++) {
            uint32_t ah[2][4], al_[2][4];
            {
                int ar = lane & 15;
                int akb = kk * 32 + ((lane >> 4) * 16);
#pragma unroll
                for (int i = 0; i < 2; i++) {
                    uint32_t off = swz((uint32_t)((wm * 32 + i * 16 + ar) * 64 + akb));
                    ldsm4(ah[i][0], ah[i][1], ah[i][2], ah[i][3], so + off);
                    if (TWOP)
                        ldsm4(al_[i][0], al_[i][1], al_[i][2], al_[i][3], so + 8192 + off);
                }
            }
            uint32_t bh[8][2];
            {
                int br = (lane & 7) + ((lane >> 4) & 1) * 8;
                int bkb = ((lane >> 3) & 1) * 16 + kk * 32;
#pragma unroll
                for (int jf = 0; jf < 4; jf++) {
                    uint32_t off = swz((uint32_t)((wn * 64 + jf * 16 + br) * 64 + bkb));
                    uint32_t r0, r1, r2, r3;
                    ldsm4(r0, r1, r2, r3, so + 16384 + off);
                    bh[2 * jf][0] = r0; bh[2 * jf][1] = r1;
                    bh[2 * jf + 1][0] = r2; bh[2 * jf + 1][1] = r3;
                }
            }
#pragma unroll
            for (int i = 0; i < 2; i++)
#pragma unroll
                for (int j = 0; j < 8; j++)
                    mma16816(acc[i][j], ah[i], bh[j]);
            if (TWOP) {
#pragma unroll
                for (int i = 0; i < 2; i++)
#pragma unroll
                    for (int j = 0; j < 8; j++)
                        mma16816(acc[i][j], al_[i], bh[j]);
            }
        }
        stg++; if (stg == 3) stg = 0;
    }

    float dsum[2][2][NOUT];
#pragma unroll
    for (int i = 0; i < 2; i++)
#pragma unroll
        for (int hf = 0; hf < 2; hf++)
#pragma unroll
            for (int o = 0; o < NOUT; o++) dsum[i][hf][o] = 0.f;

#pragma unroll
    for (int i = 0; i < 2; i++) {
#pragma unroll
        for (int j = 0; j < 8; j++) {
            int col = n0 + wn * 64 + j * 8 + (lane & 3) * 2;
            float b0 = bias[col], b1 = bias[col + 1];
            float v0 = elu1(acc[i][j][0] + b0), v1 = elu1(acc[i][j][1] + b1);
            float v2 = elu1(acc[i][j][2] + b0), v3 = elu1(acc[i][j][3] + b1);
#pragma unroll
            for (int o = 0; o < NOUT; o++) {
                float w0 = dw[o * 256 + col], w1 = dw[o * 256 + col + 1];
                dsum[i][0][o] += v0 * w0 + v1 * w1;
                dsum[i][1][o] += v2 * w0 + v3 * w1;
            }
        }
    }
#pragma unroll
    for (int i = 0; i < 2; i++)
#pragma unroll
        for (int hf = 0; hf < 2; hf++)
#pragma unroll
            for (int o = 0; o < NOUT; o++) {
                float s = dsum[i][hf][o];
                s += __shfl_xor_sync(0xffffffffu, s, 1);
                s += __shfl_xor_sync(0xffffffffu, s, 2);
                dsum[i][hf][o] = s;
            }
    if ((lane & 3) == 0) {
        const bool addb = (blockIdx.x == 0 && wn == 0);
#pragma unroll
        for (int i = 0; i < 2; i++)
#pragma unroll
            for (int hf = 0; hf < 2; hf++) {
                int row = m0 + wm * 32 + i * 16 + (lane >> 2) + hf * 8;
#pragma unroll
                for (int o = 0; o < NOUT; o++) {
                    float v = dsum[i][hf][o];
                    if (addb) v += dbias[o];
                    atomicAdd(&dout[(size_t)row * NOUT + o], v);
                }
            }
    }
}

// ======== single-pass fp16 GEMM for qk ======================================
#define QSTAGE 16384
#define QSMEM (3 * QSTAGE)
__global__ __launch_bounds__(256, 2) void gemm_qk1p(
    const __half* __restrict__ Ah, const __half* __restrict__ B,
    const float* __restrict__ bias, __half* __restrict__ Cb,
    int K, int ldC)
{
    extern __shared__ __align__(1024) char smem[];
    const uint32_t sb = smem_u32(smem);
    const int tid = threadIdx.x;
    const int lane = tid & 31;
    const int wid = tid >> 5;
    const int wm = wid & 3;
    const int wn = wid >> 2;
    const int m0 = blockIdx.y * 128;
    const int n0 = blockIdx.x * 128;

    const int nch = K >> 5;
    float acc[2][8][4] = {};
    const int lr = (tid >> 2);
    const int lc = tid & 3;

    auto issue = [&](int ci, int stg) {
        const int k0 = ci << 5;
        const uint32_t so = sb + stg * QSTAGE;
#pragma unroll
        for (int j = 0; j < 2; j++) {
            int r = lr + j * 64;
            uint32_t d = swz((uint32_t)(r * 64 + lc * 16));
            CP16(so + d,        Ah + (size_t)(m0 + r) * K + k0 + lc * 8);
            CP16(so + 8192 + d, B + (size_t)(n0 + r) * K + k0 + lc * 8);
        }
        CP_COMMIT();
    };

    issue(0, 0);
    if (nch > 1) issue(1, 1);

    int stg = 0;
    for (int ci = 0; ci < nch; ci++) {
        if (ci + 1 < nch) { CP_WAIT1(); } else { CP_WAIT0(); }
        __syncthreads();
        if (ci + 2 < nch) {
            int ns = stg + 2; if (ns >= 3) ns -= 3;
            issue(ci + 2, ns);
        }
        const uint32_t so = sb + stg * QSTAGE;
#pragma unroll
        for (int kk = 0; kk < 2; kk++) {
            uint32_t ah[2][4];
            {
                int ar = lane & 15;
                int akb = kk * 32 + ((lane >> 4) * 16);
#pragma unroll
                for (int i = 0; i < 2; i++) {
                    uint32_t off = swz((uint32_t)((wm * 32 + i * 16 + ar) * 64 + akb));
                    ldsm4(ah[i][0], ah[i][1], ah[i][2], ah[i][3], so + off);
                }
            }
            uint32_t bh[8][2];
            {
                int br = (lane & 7) + ((lane >> 4) & 1) * 8;
                int bkb = ((lane >> 3) & 1) * 16 + kk * 32;
#pragma unroll
                for (int jf = 0; jf < 4; jf++) {
                    uint32_t off = swz((uint32_t)((wn * 64 + jf * 16 + br) * 64 + bkb));
                    uint32_t r0, r1, r2, r3;
                    ldsm4(r0, r1, r2, r3, so + 8192 + off);
                    bh[2 * jf][0] = r0; bh[2 * jf][1] = r1;
                    bh[2 * jf + 1][0] = r2; bh[2 * jf + 1][1] = r3;
                }
            }
#pragma unroll
            for (int i = 0; i < 2; i++)
#pragma unroll
                for (int j = 0; j < 8; j++)
                    mma16816(acc[i][j], ah[i], bh[j]);
        }
        stg++; if (stg == 3) stg = 0;
    }

#pragma unroll
    for (int i = 0; i < 2; i++) {
        int row = m0 + wm * 32 + i * 16 + (lane >> 2);
#pragma unroll
        for (int j = 0; j < 8; j++) {
            int col = n0 + wn * 64 + j * 8 + (lane & 3) * 2;
            float b0 = bias[col], b1 = bias[col + 1];
            __half2 p0 = __floats2half2_rn(acc[i][j][0] + b0, acc[i][j][1] + b1);
            __half2 p1 = __floats2half2_rn(acc[i][j][2] + b0, acc[i][j][3] + b1);
            *reinterpret_cast<__half2*>(Cb + (size_t)row * ldC + col) = p0;
            *reinterpret_cast<__half2*>(Cb + (size_t)(row + 8) * ldC + col) = p1;
        }
    }
}

// ============ fused A-build GEMM machinery (SA=40 A layout, B single) ========
#define SA 40
#define F2_AH 0
#define F2_AL 10240
#define F2_ASTAGE 20480
#define F2_BSTAGE 8192
#define F2_BOFF (2 * F2_ASTAGE)
#define F2_TOT (F2_BOFF + 3 * F2_BSTAGE)

__device__ __forceinline__ void fused_compute_chunk_1p(
    uint32_t aBase, uint32_t bBase, int lane, int wm, int wn, float acc[2][8][4])
{
#pragma unroll
    for (int kk = 0; kk < 2; kk++) {
        uint32_t ah[2][4];
        {
            int ar = lane & 15;
            int akc = ((lane >> 4) << 3) + (kk << 4);
#pragma unroll
            for (int i = 0; i < 2; i++) {
                uint32_t off = (uint32_t)((wm * 32 + i * 16 + ar) * SA + akc) * 2;
                ldsm4(ah[i][0], ah[i][1], ah[i][2], ah[i][3], aBase + F2_AH + off);
            }
        }
        uint32_t bh[8][2];
        {
            int br = (lane & 7) + ((lane >> 4) & 1) * 8;
            int bkb = ((lane >> 3) & 1) * 16 + kk * 32;
#pragma unroll
            for (int jf = 0; jf < 4; jf++) {
                uint32_t off = swz((uint32_t)((wn * 64 + jf * 16 + br) * 64 + bkb));
                uint32_t r0, r1, r2, r3;
                ldsm4(r0, r1, r2, r3, bBase + off);
                bh[2 * jf][0] = r0; bh[2 * jf][1] = r1;
                bh[2 * jf + 1][0] = r2; bh[2 * jf + 1][1] = r3;
            }
        }
#pragma unroll
        for (int i = 0; i < 2; i++)
#pragma unroll
            for (int j = 0; j < 8; j++)
                mma16816(acc[i][j], ah[i], bh[j]);
    }
}

__device__ __forceinline__ void fused_epilogue_split(
    const float* bias, __half* Ch, __half* Cl,
    int m0, int n0, int lane, int wm, int wn, float acc[2][8][4])
{
#pragma unroll
    for (int i = 0; i < 2; i++) {
        int row = m0 + wm * 32 + i * 16 + (lane >> 2);
#pragma unroll
        for (int j = 0; j < 8; j++) {
            int col = n0 + wn * 64 + j * 8 + (lane & 3) * 2;
            float b0 = bias[col], b1 = bias[col + 1];
            float v0 = elu1(acc[i][j][0] + b0), v1 = elu1(acc[i][j][1] + b1);
            float v2 = elu1(acc[i][j][2] + b0), v3 = elu1(acc[i][j][3] + b1);
            size_t o0 = (size_t)row * HIDC + col;
            size_t o1 = (size_t)(row + 8) * HIDC + col;
            uint32_t hi, lo;
            cvt_split2(v0, v1, hi, lo);
            *reinterpret_cast<uint32_t*>(Ch + o0) = hi;
            *reinterpret_cast<uint32_t*>(Cl + o0) = lo;
            cvt_split2(v2, v3, hi, lo);
            *reinterpret_cast<uint32_t*>(Ch + o1) = hi;
            *reinterpret_cast<uint32_t*>(Cl + o1) = lo;
        }
    }
}

// ======== phi1-L1 GEMM: fp32 peA rounded to single fp16 plane in-kernel ======
#define P1A_SMEM F2_TOT
__global__ __launch_bounds__(256, 2) void gemm_phi1a(
    const float* __restrict__ peA,
    const __half* __restrict__ B,
    const float* __restrict__ bias,
    __half* __restrict__ Ch, __half* __restrict__ Cl)
{
    extern __shared__ __align__(1024) char smem[];
    const uint32_t sb = smem_u32(smem);
    const int tid = threadIdx.x;
    const int lane = tid & 31;
    const int wid = tid >> 5;
    const int wm = wid & 3;
    const int wn = wid >> 2;
    const int m0 = blockIdx.y * 128;
    const int n0 = blockIdx.x * 128;
    const int nch = KPAD1 >> 5;

    float acc[2][8][4] = {};
    float4 a_r[4];
    const int blr = tid >> 2;
    const int blc = tid & 3;

    auto issueB = [&](int ci, int s3) {
        const int k0 = ci << 5;
        const uint32_t so = sb + F2_BOFF + s3 * F2_BSTAGE;
#pragma unroll
        for (int j = 0; j < 2; j++) {
            int r = blr + j * 64;
            uint32_t d = swz((uint32_t)(r * 64 + blc * 16));
            CP16(so + d, B + (size_t)(n0 + r) * KPAD1 + k0 + blc * 8);
        }
        CP_COMMIT();
    };
    auto prefA = [&](int ci) {
        const int k0 = ci << 5;
#pragma unroll
        for (int j = 0; j < 4; j++) {
            int idx = tid + j * 256;
            int r = idx >> 3, c4 = idx & 7;
            int col = k0 + c4 * 4;
            const float* p = peA + (size_t)(m0 + r) * 514 + col;
            float4 v = make_float4(0.f, 0.f, 0.f, 0.f);
            if (col + 3 < 514) {
                float2 x = *reinterpret_cast<const float2*>(p);
                float2 y = *reinterpret_cast<const float2*>(p + 2);
                v = make_float4(x.x, x.y, y.x, y.y);
            } else {
                if (col + 0 < 514) v.x = p[0];
                if (col + 1 < 514) v.y = p[1];
                if (col + 2 < 514) v.z = p[2];
                if (col + 3 < 514) v.w = p[3];
            }
            a_r[j] = v;
        }
    };

    issueB(0, 0);
    issueB(1, 1);
    prefA(0);

    int s3 = 0;
    for (int ci = 0; ci < nch; ci++) {
        const int s2 = ci & 1;
        if (ci + 1 < nch) { CP_WAIT1(); } else { CP_WAIT0(); }
        __syncthreads();
        if (ci + 2 < nch) {
            int ns = s3 + 2; if (ns >= 3) ns -= 3;
            issueB(ci + 2, ns);
        }
#pragma unroll
        for (int j = 0; j < 4; j++) {
            int idx = tid + j * 256;
            int r = idx >> 3, c4 = idx & 7;
            __half2 p01 = __floats2half2_rn(a_r[j].x, a_r[j].y);
            __half2 p23 = __floats2half2_rn(a_r[j].z, a_r[j].w);
            uint32_t o = (uint32_t)(r * SA + c4 * 4) * 2;
            *reinterpret_cast<uint2*>(smem + s2 * F2_ASTAGE + F2_AH + o) =
                make_uint2(*reinterpret_cast<uint32_t*>(&p01),
                           *reinterpret_cast<uint32_t*>(&p23));
        }
        if (ci + 1 < nch) prefA(ci + 1);
        __syncthreads();
        fused_compute_chunk_1p(sb + s2 * F2_ASTAGE, sb + F2_BOFF + s3 * F2_BSTAGE,
                               lane, wm, wn, acc);
        s3++; if (s3 == 3) s3 = 0;
    }

    fused_epilogue_split(bias, Ch, Cl, m0, n0, lane, wm, wn, acc);
}

// ======== alt2: dual-source GEMM, fully single-pass ==========================
// C = elu( pe@P2W1^T + h1h@Wc3m^T + kmP[group] ), split output.
// Phase 1: 16 chunks over pe (fp32 -> fp16 round). Phase 2: 8 chunks over h1h.
#define ALT2_KMP 8192
#define ALT2_SMEM (ALT2_KMP + F2_TOT)
__global__ __launch_bounds__(256, 2) void gemm_alt2(
    const float* __restrict__ pe,
    const __half* __restrict__ h1h,
    const float* __restrict__ kmP,
    const __half* __restrict__ B1, const __half* __restrict__ B2,
    __half* __restrict__ Ch, __half* __restrict__ Cl)
{
    extern __shared__ __align__(1024) char smem[];
    float* kmS = reinterpret_cast<float*>(smem);
    char* sdata = smem + ALT2_KMP;
    const uint32_t sb = smem_u32(smem) + ALT2_KMP;
    const int tid = threadIdx.x;
    const int lane = tid & 31;
    const int wid = tid >> 5;
    const int wm = wid & 3;
    const int wn = wid >> 2;
    const int m0 = blockIdx.y * 128;
    const int n0 = blockIdx.x * 128;
    const int nch = 24;   // 16 pe + 8 h1, all single-pass

    float acc[2][8][4] = {};
    uint2 a_r[4];
    const int blr = tid >> 2;
    const int blc = tid & 3;

    auto issueB = [&](int ci, int s3) {
        const uint32_t so = sb + F2_BOFF + s3 * F2_BSTAGE;
#pragma unroll
        for (int j = 0; j < 2; j++) {
            int r = blr + j * 64;
            uint32_t d = swz((uint32_t)(r * 64 + blc * 16));
            if (ci < 16)
                CP16(so + d, B1 + (size_t)(n0 + r) * 512 + (ci << 5) + blc * 8);
            else
                CP16(so + d, B2 + (size_t)(n0 + r) * 256 + ((ci - 16) << 5) + blc * 8);
        }
        CP_COMMIT();
    };
    auto prefA = [&](int ci) {
#pragma unroll
        for (int j = 0; j < 4; j++) {
            int idx = tid + j * 256;
            int r = idx >> 3, c4 = idx & 7;
            if (ci < 16) {
                size_t ao = (size_t)(m0 + r) * 512 + (ci << 5) + c4 * 4;
                float4 v = *reinterpret_cast<const float4*>(pe + ao);
                __half2 p01 = __floats2half2_rn(v.x, v.y);
                __half2 p23 = __floats2half2_rn(v.z, v.w);
                a_r[j] = make_uint2(*reinterpret_cast<uint32_t*>(&p01),
                                    *reinterpret_cast<uint32_t*>(&p23));
            } else {
                size_t ao = (size_t)(m0 + r) * 256 + ((ci - 16) << 5) + c4 * 4;
                a_r[j] = *reinterpret_cast<const uint2*>(h1h + ao);
            }
        }
    };

    const int g0 = m0 >> 4;
    for (int i = tid; i < 2048; i += 256)
        kmS[i] = kmP[(size_t)(g0 + (i >> 8)) * 256 + (i & 255)];

    issueB(0, 0);
    issueB(1, 1);
    prefA(0);

    int s3 = 0;
    for (int ci = 0; ci < nch; ci++) {
        const int s2 = ci & 1;
        if (ci + 1 < nch) { CP_WAIT1(); } else { CP_WAIT0(); }
        __syncthreads();
        if (ci + 2 < nch) {
            int ns = s3 + 2; if (ns >= 3) ns -= 3;
            issueB(ci + 2, ns);
        }
#pragma unroll
        for (int j = 0; j < 4; j++) {
            int idx = tid + j * 256;
            int r = idx >> 3, c4 = idx & 7;
            uint32_t o = (uint32_t)(r * SA + c4 * 4) * 2;
            *reinterpret_cast<uint2*>(sdata + s2 * F2_ASTAGE + F2_AH + o) = a_r[j];
        }
        if (ci + 1 < nch) prefA(ci + 1);
        __syncthreads();
        fused_compute_chunk_1p(sb + s2 * F2_ASTAGE, sb + F2_BOFF + s3 * F2_BSTAGE,
                               lane, wm, wn, acc);
        s3++; if (s3 == 3) s3 = 0;
    }

#pragma unroll
    for (int i = 0; i < 2; i++) {
        int rl = wm * 32 + i * 16 + (lane >> 2);
        int row = m0 + rl;
#pragma unroll
        for (int j = 0; j < 8; j++) {
            int col = n0 + wn * 64 + j * 8 + (lane & 3) * 2;
            float b0a = kmS[(rl >> 4) * 256 + col];
            float b1a = kmS[(rl >> 4) * 256 + col + 1];
            float b0b = kmS[((rl + 8) >> 4) * 256 + col];
            float b1b = kmS[((rl + 8) >> 4) * 256 + col + 1];
            float v0 = elu1(acc[i][j][0] + b0a), v1 = elu1(acc[i][j][1] + b1a);
            float v2 = elu1(acc[i][j][2] + b0b), v3 = elu1(acc[i][j][3] + b1b);
            size_t o0 = (size_t)row * HIDC + col;
            size_t o1 = (size_t)(row + 8) * HIDC + col;
            uint32_t hi, lo;
            cvt_split2(v0, v1, hi, lo);
            *reinterpret_cast<uint32_t*>(Ch + o0) = hi;
            *reinterpret_cast<uint32_t*>(Cl + o0) = lo;
            cvt_split2(v2, v3, hi, lo);
            *reinterpret_cast<uint32_t*>(Ch + o1) = hi;
            *reinterpret_cast<uint32_t*>(Cl + o1) = lo;
        }
    }
}

// ---------------- multi-segment weight convert ----------------
#define MAXSEG 9
struct ConvSegs {
    const float* src[MAXSEG];
    int dstoff[MAXSEG];
    int C[MAXSEG];
    int Cp[MAXSEG];
    int rows[MAXSEG];
    int n;
};
__global__ __launch_bounds__(256) void conv_multi(
    ConvSegs p, __half* __restrict__ dst)
{
    const uint32_t stride = gridDim.x * 256u;
    const uint32_t base = blockIdx.x * 256u + threadIdx.x;
    for (int s = 0; s < p.n; s++) {
        const float* src = p.src[s];
        const int C = p.C[s], Cp = p.Cp[s], off = p.dstoff[s];
        const uint32_t tot = (uint32_t)p.rows[s] * Cp;
        for (uint32_t i = base; i < tot; i += stride) {
            uint32_t r = i / (uint32_t)Cp;
            int c = (int)(i - r * (uint32_t)Cp);
            float v = (c < C) ? src[(size_t)r * C + c] : 0.f;
            dst[off + i] = __float2half(v);
        }
    }
}

// ---------------- compose all: {Wqk, Wv01, P2W1} x W4 -----------------------
__global__ __launch_bounds__(256) void compose_all(
    const float* __restrict__ wqk, const float* __restrict__ wv01,
    const float* __restrict__ p2w1, const float* __restrict__ w4,
    const float* __restrict__ b4, const float* __restrict__ battn,
    const float* __restrict__ p2b1,
    __half* __restrict__ wp,
    float* __restrict__ bc, float* __restrict__ bv2, float* __restrict__ bb)
{
    __shared__ float wrow[512];
    const int blk = blockIdx.x;
    const int tid = threadIdx.x;
    const float* src;
    const float* bin;
    float* bout;
    float scale;
    int outoff, n;
    if (blk < 1024)      { src = wqk;  n = blk;        scale = 1.f;      outoff = OW_WC;  bin = battn;        bout = bc;  }
    else if (blk < 1536) { src = wv01; n = blk - 1024; scale = 1.f;      outoff = OW_WVC; bin = battn + 1024; bout = bv2; }
    else                 { src = p2w1; n = blk - 1536; scale = -0.0625f; outoff = OW_WC3; bin = p2b1;         bout = bb;  }
    wrow[tid] = src[(size_t)n * 512 + tid];
    wrow[tid + 256] = src[(size_t)n * 512 + tid + 256];
    __syncthreads();
    float acc = 0.f;
#pragma unroll 8
    for (int j = 0; j < 512; j++)
        acc += wrow[j] * w4[(size_t)j * 256 + tid];
    wp[outoff + (size_t)n * 256 + tid] = __float2half(acc * scale);
    if (tid < 32) {
        float s = 0.f;
        for (int j = tid; j < 512; j += 32) s += wrow[j] * b4[j];
#pragma unroll
        for (int o = 16; o > 0; o >>= 1) s += __shfl_xor_sync(0xffffffffu, s, o);
        if (tid == 0) bout[n] = s * scale + bin[n];
    }
}

// ---------------- zero output ----------------
__global__ __launch_bounds__(256) void zero_out(float* __restrict__ p, int n) {
    int i = blockIdx.x * 256 + threadIdx.x;
    if (i < n) p[i] = 0.f;
}

// ---------------- attention v4: mma scores, h1-based hw ---------------------
#define AROW 1032
__global__ __launch_bounds__(256) void attn4_kernel(
    const __half* __restrict__ qk,
    const __half* __restrict__ h1h, const __half* __restrict__ h1l,
    __half* __restrict__ hwh, __half* __restrict__ hwl)
{
    const int g = blockIdx.x;
    const int tid = threadIdx.x;
    const int lane = tid & 31;
    const int wid = tid >> 5;
    __shared__ __align__(16) __half qks[16 * AROW];
    __shared__ float sc[2][16][17];
    __shared__ float cw[2][16];
    const uint32_t sbq = smem_u32(qks);

    {
        const uint4* src = reinterpret_cast<const uint4*>(qk + (size_t)g * GSZ * 1024);
#pragma unroll
        for (int t = 0; t < 8; t++) {
            int idx = tid + t * 256;
            int row = idx >> 7;
            int c8 = idx & 127;
            *reinterpret_cast<uint4*>(qks + row * AROW + c8 * 8) = src[idx];
        }
    }
    __syncthreads();

    if (wid < 2) {
        const int h = wid;
        float accS[2][4] = {};
        const uint32_t qb = (uint32_t)(h * 256) * 2;
        const uint32_t kb = (uint32_t)(512 + h * 256) * 2;
#pragma unroll
        for (int ks = 0; ks < 16; ks++) {
            uint32_t a[4];
            {
                int ar = lane & 15;
                uint32_t addr = sbq + (uint32_t)(ar * AROW) * 2 + qb + ks * 32 + (lane >> 4) * 16;
                ldsm4(a[0], a[1], a[2], a[3], addr);
            }
            uint32_t b0[2], b1[2];
            {
                int br = (lane & 7) + ((lane >> 4) & 1) * 8;
                uint32_t addr = sbq + (uint32_t)(br * AROW) * 2 + kb + ks * 32 + ((lane >> 3) & 1) * 16;
                uint32_t r0, r1, r2, r3;
                ldsm4(r0, r1, r2, r3, addr);
                b0[0] = r0; b0[1] = r1;
                b1[0] = r2; b1[1] = r3;
            }
            mma16816(accS[0], a, b0);
            mma16816(accS[1], a, b1);
        }
        {
            int row = lane >> 2;
            int col = (lane & 3) * 2;
#pragma unroll
            for (int j = 0; j < 2; j++) {
                sc[h][row][j * 8 + col]     = accS[j][0] * 0.0625f;
                sc[h][row][j * 8 + col + 1] = accS[j][1] * 0.0625f;
                sc[h][row + 8][j * 8 + col]     = accS[j][2] * 0.0625f;
                sc[h][row + 8][j * 8 + col + 1] = accS[j][3] * 0.0625f;
            }
        }
    }
    __syncthreads();

    if (tid < 32) {
        int h = tid >> 4, tq = tid & 15;
        float mx = -1e30f;
#pragma unroll
        for (int tk = 0; tk < 16; tk++) mx = fmaxf(mx, sc[h][tq][tk]);
        float s = 0.f;
#pragma unroll
        for (int tk = 0; tk < 16; tk++) {
            float e = expf(sc[h][tq][tk] - mx);
            sc[h][tq][tk] = e;
            s += e;
        }
        float inv = 1.f / s;
#pragma unroll
        for (int tk = 0; tk < 16; tk++) sc[h][tq][tk] *= inv;
    }
    __syncthreads();
    if (tid < 32) {
        int h = tid >> 4, tk = tid & 15;
        float s = 0.f;
#pragma unroll
        for (int tq = 0; tq < 16; tq++) s += sc[h][tq][tk];
        cw[h][tk] = s * 0.0625f;
    }
    __syncthreads();

    if (tid < 128) {
        int d2 = tid * 2;
        const __half* xbh = h1h + (size_t)g * GSZ * 256 + d2;
        const __half* xbl = h1l + (size_t)g * GSZ * 256 + d2;
        float a0[2] = {}, a1[2] = {};
#pragma unroll
        for (int tk = 0; tk < 16; tk++) {
            uint32_t vh = *reinterpret_cast<const uint32_t*>(xbh + tk * 256);
            uint32_t vl = *reinterpret_cast<const uint32_t*>(xbl + tk * 256);
            float2 hh = h2f2(vh), ll = h2f2(vl);
            float x0 = hh.x + ll.x, x1 = hh.y + ll.y;
            float w0 = cw[0][tk], w1 = cw[1][tk];
            a0[0] += w0 * x0; a0[1] += w0 * x1;
            a1[0] += w1 * x0; a1[1] += w1 * x1;
        }
        uint32_t hi, lo;
        size_t o0 = (size_t)g * HIDC + d2;
        cvt_split2(a0[0], a0[1], hi, lo);
        *reinterpret_cast<uint32_t*>(hwh + o0) = hi;
        *reinterpret_cast<uint32_t*>(hwl + o0) = lo;
        size_t o1 = (size_t)NGR * HIDC + o0;
        cvt_split2(a1[0], a1[1], hi, lo);
        *reinterpret_cast<uint32_t*>(hwh + o1) = hi;
        *reinterpret_cast<uint32_t*>(hwl + o1) = lo;
    }
}

// ================================================================ host launch
extern "C" void kernel_launch(void* const* d_in, const int* in_sizes, int n_in,
                              void* d_out, int out_size)
{
    const float* pe       = (const float*)d_in[0];
    const float* peA      = (const float*)d_in[1];
    const float* attn_in_w  = (const float*)d_in[2];
    const float* attn_in_b  = (const float*)d_in[3];
    const float* attn_out_w = (const float*)d_in[4];
    const float* attn_out_b = (const float*)d_in[5];
    const float* p1w1 = (const float*)d_in[6];  const float* p1b1 = (const float*)d_in[7];
    const float* p1w2 = (const float*)d_in[8];  const float* p1b2 = (const float*)d_in[9];
    const float* p1w3 = (const float*)d_in[10]; const float* p1b3 = (const float*)d_in[11];
    const float* p1w4 = (const float*)d_in[12]; const float* p1b4 = (const float*)d_in[13];
    const float* gw1 = (const float*)d_in[14];  const float* gb1 = (const float*)d_in[15];
    const float* gw2 = (const float*)d_in[16];  const float* gb2 = (const float*)d_in[17];
    const float* gw3 = (const float*)d_in[18];  const float* gb3 = (const float*)d_in[19];
    const float* gw4 = (const float*)d_in[20];  const float* gb4 = (const float*)d_in[21];
    const float* p2w1 = (const float*)d_in[22]; const float* p2b1 = (const float*)d_in[23];
    const float* p2w2 = (const float*)d_in[24]; const float* p2b2 = (const float*)d_in[25];
    const float* p2w3 = (const float*)d_in[26]; const float* p2b3 = (const float*)d_in[27];
    float* out = (float*)d_out;

    #define SYM(T, v, s) T* v; cudaGetSymbolAddress((void**)&v, s)
    SYM(__half, h1h, g_h1h);   SYM(__half, h1l, g_h1l);
    SYM(__half, h2h, g_h2h);   SYM(__half, h2l, g_h2l);
    SYM(__half, qk, g_qk);
    SYM(__half, xwh, g_xwh);   SYM(__half, xwl, g_xwl);
    SYM(__half, omh, g_omh);   SYM(__half, oml, g_oml);
    SYM(__half, kmh, g_kmh);   SYM(__half, kml, g_kml);
    SYM(float, kmpf, g_kmp);
    SYM(__half, hgah, g_hgah); SYM(__half, hgal, g_hgal);
    SYM(__half, hgbh, g_hgbh); SYM(__half, hgbl, g_hgbl);
    SYM(__half, wp, g_wp);
    SYM(float, bc, g_bc);
    SYM(float, bv2, g_bv2);
    SYM(float, bb, g_bb);

    cudaFuncSetAttribute(gemm_2p<1,false,true>, cudaFuncAttributeMaxDynamicSharedMemorySize, SMEM_TOT);
    cudaFuncSetAttribute(gemm_2p<2,false,true>, cudaFuncAttributeMaxDynamicSharedMemorySize, SMEM_TOT);
    cudaFuncSetAttribute(gemm_2p<0,false,true>, cudaFuncAttributeMaxDynamicSharedMemorySize, SMEM_TOT);
    cudaFuncSetAttribute(gemm_2p<0,true,false>, cudaFuncAttributeMaxDynamicSharedMemorySize, SMEM_TOT);
    cudaFuncSetAttribute(gemm_2p_h2, cudaFuncAttributeMaxDynamicSharedMemorySize, SMEM_TOT);
    cudaFuncSetAttribute(gemm_dot<1,true>,  cudaFuncAttributeMaxDynamicSharedMemorySize, SMEM_TOT);
    cudaFuncSetAttribute(gemm_dot<2,false>, cudaFuncAttributeMaxDynamicSharedMemorySize, SMEM_TOT);
    cudaFuncSetAttribute(gemm_qk1p, cudaFuncAttributeMaxDynamicSharedMemorySize, QSMEM);
    cudaFuncSetAttribute(gemm_phi1a, cudaFuncAttributeMaxDynamicSharedMemorySize, P1A_SMEM);
    cudaFuncSetAttribute(gemm_alt2, cudaFuncAttributeMaxDynamicSharedMemorySize, ALT2_SMEM);

    const int TB = 256;
    #define GRID(Mv, Nv) dim3((Nv) / 128, (Mv) / 128)

    // side stream + events for graph branches
    cudaStream_t s2;
    cudaStreamCreateWithFlags(&s2, cudaStreamNonBlocking);
    cudaEvent_t e0, e1, e2, e3;
    cudaEventCreateWithFlags(&e0, cudaEventDisableTiming);
    cudaEventCreateWithFlags(&e1, cudaEventDisableTiming);
    cudaEventCreateWithFlags(&e2, cudaEventDisableTiming);
    cudaEventCreateWithFlags(&e3, cudaEventDisableTiming);

    // ---- main stream: zero output ----
    zero_out<<<(out_size + 255) / 256, TB>>>(out, out_size);

    // fork A: side stream does non-phi1 weight prep
    cudaEventRecord(e0, 0);
    cudaStreamWaitEvent(s2, e0, 0);
    {
        ConvSegs s = {};
        int n = 0;
        auto add = [&](const float* src, int off, int R, int C, int Cp) {
            s.src[n] = src; s.dstoff[n] = off; s.rows[n] = R; s.C[n] = C; s.Cp[n] = Cp; n++;
        };
        add(attn_out_w, OW_WOUT, 512, 512, 512);
        add(gw1, OW_GW1, 256, 512, 512);
        add(gw2, OW_GW2, 256, 256, 256);
        add(gw3, OW_GW3, 256, 256, 256);
        add(p2w1, OW_P2W1, 256, 512, 512);
        add(p2w2, OW_P2W2, 256, 256, 256);
        s.n = n;
        conv_multi<<<512, TB, 0, s2>>>(s, wp);
    }
    compose_all<<<1792, TB, 0, s2>>>(attn_in_w, attn_in_w + (size_t)1024 * 512, p2w1,
                                     p1w4, p1b4, attn_in_b, p2b1,
                                     wp, bc, bv2, bb);
    cudaEventRecord(e1, s2);

    // ---- main: phi1 weight converts + phi1 chain ----
    {
        ConvSegs s = {};
        int n = 0;
        auto add = [&](const float* src, int off, int R, int C, int Cp) {
            s.src[n] = src; s.dstoff[n] = off; s.rows[n] = R; s.C[n] = C; s.Cp[n] = Cp; n++;
        };
        add(p1w1, OW_P1W1, 256, 514, KPAD1);
        add(p1w2, OW_P1W2, 256, 256, 256);
        add(p1w3, OW_P1W3, 256, 256, 256);
        s.n = n;
        conv_multi<<<512, TB>>>(s, wp);
    }
    gemm_phi1a<<<GRID(NTOK, 256), TB, P1A_SMEM>>>(
        peA, wp + OW_P1W1, p1b1, h1h, h1l);
    gemm_2p<2,false,true><<<GRID(NTOK, HIDC), TB, SMEM_TOT>>>(
        h1h, h1l, wp + OW_P1W2, p1b2, nullptr, h2h, h2l, HIDC, HIDC);
    gemm_2p<1,false,true><<<GRID(NTOK, HIDC), TB, SMEM_TOT>>>(
        h2h, h2l, wp + OW_P1W3, p1b3, nullptr, h1h, h1l, HIDC, HIDC);

    // join A
    cudaStreamWaitEvent(0, e1, 0);

    // qk = h1 @ Wc^T + bc (single-pass fp16, K=256)
    gemm_qk1p<<<GRID(NTOK, 1024), TB, QSMEM>>>(
        h1h, wp + OW_WC, bc, qk, HIDC, 1024);
    attn4_kernel<<<NGR, TB>>>(qk, h1h, h1l, xwh, xwl);
    gemm_2p_h2<<<GRID(NGR, 512), TB, SMEM_TOT>>>(
        xwh, xwl, xwh + (size_t)NGR * HIDC, xwl + (size_t)NGR * HIDC,
        wp + OW_WVC, wp + OW_WVC + 65536, bv2, omh, oml);
    gemm_2p<0,false,true><<<GRID(NGR, EFULL), TB, SMEM_TOT>>>(
        omh, oml, wp + OW_WOUT, attn_out_b, nullptr, kmh, kml, EFULL, EFULL);

    // fork B: g-head chain on side stream (writes out[0..NGR))
    cudaEventRecord(e2, 0);
    cudaStreamWaitEvent(s2, e2, 0);
    gemm_2p<1,false,true><<<GRID(NGR, HIDC), TB, SMEM_TOT, s2>>>(
        kmh, kml, wp + OW_GW1, gb1, nullptr, hgah, hgal, EFULL, HIDC);
    gemm_2p<1,false,true><<<GRID(NGR, HIDC), TB, SMEM_TOT, s2>>>(
        hgah, hgal, wp + OW_GW2, gb2, nullptr, hgbh, hgbl, HIDC, HIDC);
    gemm_dot<1,true><<<GRID(NGR, HIDC), TB, SMEM_TOT, s2>>>(
        hgbh, hgbl, wp + OW_GW3, gb3, gw4, gb4, out, HIDC);
    cudaEventRecord(e3, s2);

    // ---- main: alt path (writes out[NGR..)) ----
    gemm_2p<0,true,false><<<GRID(NGR, 256), TB, SMEM_TOT>>>(
        kmh, kml, wp + OW_P2W1, bb, kmpf, nullptr, nullptr, EFULL, HIDC);
    gemm_alt2<<<GRID(NTOK, 256), TB, ALT2_SMEM>>>(
        pe, h1h, kmpf, wp + OW_P2W1, wp + OW_WC3, h2h, h2l);
    gemm_dot<2,false><<<GRID(NTOK, HIDC), TB, SMEM_TOT>>>(
        h2h, h2l, wp + OW_P2W2, p2b2, p2w3, p2b3, out + NGR, HIDC);

    // join B
    cudaStreamWaitEvent(0, e3, 0);
}

// round 17
// speedup vs baseline: 1.0220x; 1.0220x over previous
#include <cuda_runtime.h>
#include <cuda_fp16.h>
#include <cstdint>
#include <math.h>

// Problem constants
#define NTOK  65536
#define EFULL 512
#define HIDC  256
#define NGR   4096
#define GSZ   16
#define KPAD1 544          // 514 padded to %32

// ---------------- scratch (__device__ globals) ----------------
__device__ __half g_h1h[(size_t)NTOK * HIDC];
__device__ __half g_h1l[(size_t)NTOK * HIDC];
__device__ __half g_h2h[(size_t)NTOK * HIDC];
__device__ __half g_h2l[(size_t)NTOK * HIDC];   // reused as alt2 lo-out only
__device__ __half g_qk[(size_t)NTOK * 1024];
__device__ __half g_xwh[(size_t)2 * NGR * HIDC];
__device__ __half g_xwl[(size_t)2 * NGR * HIDC];
__device__ __half g_omh[(size_t)NGR * EFULL];
__device__ __half g_oml[(size_t)NGR * EFULL];
__device__ __half g_kmh[(size_t)NGR * EFULL];
__device__ __half g_kml[(size_t)NGR * EFULL];
__device__ float  g_kmp[(size_t)NGR * HIDC];
__device__ __half g_hgah[(size_t)NGR * HIDC];
__device__ __half g_hgal[(size_t)NGR * HIDC];
__device__ __half g_hgbh[(size_t)NGR * HIDC];
__device__ __half g_hgbl[(size_t)NGR * HIDC];
__device__ float  g_bc[1024];
__device__ float  g_bv2[512];
__device__ float  g_bb[256];

// weight pool (single fp16). offsets in elements:
#define OW_P1W1 0                 // 256x544
#define OW_P1W2 139264            // 256x256
#define OW_P1W3 204800            // 256x256
#define OW_WOUT 270336            // 512x512
#define OW_GW1  532480            // 256x512
#define OW_GW2  663552            // 256x256
#define OW_GW3  729088            // 256x256
#define OW_P2W1 794624            // 256x512
#define OW_P2W2 925696            // 256x256
#define OW_WC   991232            // Wqk@W4: 1024x256
#define OW_WVC  1253376           // Wv01@W4: 512x256
#define OW_WC3  1384448           // -(P2W1@W4)/16: 256x256
#define OW_TOT  1449984
__device__ __half g_wp[OW_TOT];

__device__ __forceinline__ float elu1(float x) {
    return x > 0.f ? x : (expf(x) - 1.f);
}
__device__ __forceinline__ uint32_t smem_u32(const void* p) {
    uint32_t a;
    asm("{ .reg .u64 t; cvta.to.shared.u64 t, %1; cvt.u32.u64 %0, t; }" : "=r"(a) : "l"(p));
    return a;
}
__device__ __forceinline__ void ldsm4(uint32_t& r0, uint32_t& r1, uint32_t& r2, uint32_t& r3,
                                      uint32_t addr) {
    asm volatile("ldmatrix.sync.aligned.m8n8.x4.shared.b16 {%0,%1,%2,%3}, [%4];"
                 : "=r"(r0), "=r"(r1), "=r"(r2), "=r"(r3) : "r"(addr));
}
__device__ __forceinline__ void mma16816(float* c, const uint32_t* a, const uint32_t* b) {
    asm volatile("mma.sync.aligned.m16n8k16.row.col.f32.f16.f16.f32 "
                 "{%0,%1,%2,%3}, {%4,%5,%6,%7}, {%8,%9}, {%0,%1,%2,%3};"
                 : "+f"(c[0]), "+f"(c[1]), "+f"(c[2]), "+f"(c[3])
                 : "r"(a[0]), "r"(a[1]), "r"(a[2]), "r"(a[3]), "r"(b[0]), "r"(b[1]));
}
__device__ __forceinline__ void cvt_split2(float a, float b, uint32_t& hi, uint32_t& lo) {
    __half2 h = __floats2half2_rn(a, b);
    float2 hf = __half22float2(h);
    __half2 l = __floats2half2_rn(a - hf.x, b - hf.y);
    hi = *reinterpret_cast<uint32_t*>(&h);
    lo = *reinterpret_cast<uint32_t*>(&l);
}
__device__ __forceinline__ float2 h2f2(uint32_t u) {
    return __half22float2(*reinterpret_cast<__half2*>(&u));
}
__device__ __forceinline__ uint32_t swz(uint32_t x) { return x ^ ((x >> 3) & 0x70); }

#define CP16(dst, src) \
    asm volatile("cp.async.cg.shared.global [%0], [%1], 16;" :: "r"(dst), "l"(src))
#define CP_COMMIT() asm volatile("cp.async.commit_group;" ::: "memory")
#define CP_WAIT1()  asm volatile("cp.async.wait_group 1;" ::: "memory")
#define CP_WAIT0()  asm volatile("cp.async.wait_group 0;" ::: "memory")

// ======== fp16 NT GEMM: A hi(/lo) planes, B single fp16 ======================
// WMODE: 0 = fp32 C, 1 = split Ch/Cl, 2 = single fp16 Ch
// TWOP:  true = A read as exact hi+lo split (2 mma passes)
#define STAGE 24576
#define SMEM_TOT (3 * STAGE)

template <int EPI, int WMODE, bool TWOP>
__global__ __launch_bounds__(256, 2) void gemm_2p(
    const __half* __restrict__ Ah, const __half* __restrict__ Al,
    const __half* __restrict__ B,
    const float* __restrict__ bias, float* __restrict__ C,
    __half* __restrict__ Ch, __half* __restrict__ Cl,
    int K, int ldC)
{
    extern __shared__ __align__(1024) char smem[];
    const uint32_t sb = smem_u32(smem);
    const int tid = threadIdx.x;
    const int lane = tid & 31;
    const int wid = tid >> 5;
    const int wm = wid & 3;
    const int wn = wid >> 2;
    const int m0 = blockIdx.y * 128;
    const int n0 = blockIdx.x * 128;

    const int nch = K >> 5;
    float acc[2][8][4] = {};
    const int lr = (tid >> 2);
    const int lc = tid & 3;

    auto issue = [&](int ci, int stg) {
        const int k0 = ci << 5;
        const uint32_t so = sb + stg * STAGE;
#pragma unroll
        for (int j = 0; j < 2; j++) {
            int r = lr + j * 64;
            uint32_t d = swz((uint32_t)(r * 64 + lc * 16));
            size_t ao = (size_t)(m0 + r) * K + k0 + lc * 8;
            size_t bo = (size_t)(n0 + r) * K + k0 + lc * 8;
            CP16(so + d, Ah + ao);
            if (TWOP) CP16(so + 8192 + d, Al + ao);
            CP16(so + 16384 + d, B + bo);
        }
        CP_COMMIT();
    };

    issue(0, 0);
    if (nch > 1) issue(1, 1);

    int stg = 0;
    for (int ci = 0; ci < nch; ci++) {
        if (ci + 1 < nch) { CP_WAIT1(); } else { CP_WAIT0(); }
        __syncthreads();
        if (ci + 2 < nch) {
            int ns = stg + 2; if (ns >= 3) ns -= 3;
            issue(ci + 2, ns);
        }
        const uint32_t so = sb + stg * STAGE;
#pragma unroll
        for (int kk = 0; kk < 2; kk++) {
            uint32_t ah[2][4], al_[2][4];
            {
                int ar = lane & 15;
                int akb = kk * 32 + ((lane >> 4) * 16);
#pragma unroll
                for (int i = 0; i < 2; i++) {
                    uint32_t off = swz((uint32_t)((wm * 32 + i * 16 + ar) * 64 + akb));
                    ldsm4(ah[i][0], ah[i][1], ah[i][2], ah[i][3], so + off);
                    if (TWOP)
                        ldsm4(al_[i][0], al_[i][1], al_[i][2], al_[i][3], so + 8192 + off);
                }
            }
            uint32_t bh[8][2];
            {
                int br = (lane & 7) + ((lane >> 4) & 1) * 8;
                int bkb = ((lane >> 3) & 1) * 16 + kk * 32;
#pragma unroll
                for (int jf = 0; jf < 4; jf++) {
                    uint32_t off = swz((uint32_t)((wn * 64 + jf * 16 + br) * 64 + bkb));
                    uint32_t r0, r1, r2, r3;
                    ldsm4(r0, r1, r2, r3, so + 16384 + off);
                    bh[2 * jf][0] = r0; bh[2 * jf][1] = r1;
                    bh[2 * jf + 1][0] = r2; bh[2 * jf + 1][1] = r3;
                }
            }
#pragma unroll
            for (int i = 0; i < 2; i++)
#pragma unroll
                for (int j = 0; j < 8; j++)
                    mma16816(acc[i][j], ah[i], bh[j]);
            if (TWOP) {
#pragma unroll
                for (int i = 0; i < 2; i++)
#pragma unroll
                    for (int j = 0; j < 8; j++)
                        mma16816(acc[i][j], al_[i], bh[j]);
            }
        }
        stg++; if (stg == 3) stg = 0;
    }

#pragma unroll
    for (int i = 0; i < 2; i++) {
        int row = m0 + wm * 32 + i * 16 + (lane >> 2);
#pragma unroll
        for (int j = 0; j < 8; j++) {
            int col = n0 + wn * 64 + j * 8 + (lane & 3) * 2;
            float b0 = bias[col], b1 = bias[col + 1];
            float v0 = acc[i][j][0] + b0, v1 = acc[i][j][1] + b1;
            float v2 = acc[i][j][2] + b0, v3 = acc[i][j][3] + b1;
            if (EPI >= 1) { v0 = elu1(v0); v1 = elu1(v1); v2 = elu1(v2); v3 = elu1(v3); }
            if (EPI == 2) { v0 = elu1(v0); v1 = elu1(v1); v2 = elu1(v2); v3 = elu1(v3); }
            size_t o0 = (size_t)row * ldC + col;
            size_t o1 = (size_t)(row + 8) * ldC + col;
            if (WMODE == 0) {
                *reinterpret_cast<float2*>(C + o0) = make_float2(v0, v1);
                *reinterpret_cast<float2*>(C + o1) = make_float2(v2, v3);
            } else if (WMODE == 1) {
                uint32_t hi, lo;
                cvt_split2(v0, v1, hi, lo);
                *reinterpret_cast<uint32_t*>(Ch + o0) = hi;
                *reinterpret_cast<uint32_t*>(Cl + o0) = lo;
                cvt_split2(v2, v3, hi, lo);
                *reinterpret_cast<uint32_t*>(Ch + o1) = hi;
                *reinterpret_cast<uint32_t*>(Cl + o1) = lo;
            } else {
                __half2 p0 = __floats2half2_rn(v0, v1);
                __half2 p1 = __floats2half2_rn(v2, v3);
                *reinterpret_cast<__half2*>(Ch + o0) = p0;
                *reinterpret_cast<__half2*>(Ch + o1) = p1;
            }
        }
    }
}

// ======== head-fused o_mean GEMM: per-block A/B select by n0 =================
__global__ __launch_bounds__(256, 2) void gemm_2p_h2(
    const __half* __restrict__ A0h, const __half* __restrict__ A0l,
    const __half* __restrict__ A1h, const __half* __restrict__ A1l,
    const __half* __restrict__ B0, const __half* __restrict__ B1,
    const float* __restrict__ bias,
    __half* __restrict__ Ch, __half* __restrict__ Cl)
{
    extern __shared__ __align__(1024) char smem[];
    const uint32_t sb = smem_u32(smem);
    const int tid = threadIdx.x;
    const int lane = tid & 31;
    const int wid = tid >> 5;
    const int wm = wid & 3;
    const int wn = wid >> 2;
    const int m0 = blockIdx.y * 128;
    const int n0 = blockIdx.x * 128;
    const int K = 256, ldC = 512;
    const bool h1sel = (n0 >= 256);
    const __half* Ah = h1sel ? A1h : A0h;
    const __half* Al = h1sel ? A1l : A0l;
    const __half* B  = h1sel ? B1 : B0;
    const int nb = n0 & 255;

    const int nch = K >> 5;
    float acc[2][8][4] = {};
    const int lr = (tid >> 2);
    const int lc = tid & 3;

    auto issue = [&](int ci, int stg) {
        const int k0 = ci << 5;
        const uint32_t so = sb + stg * STAGE;
#pragma unroll
        for (int j = 0; j < 2; j++) {
            int r = lr + j * 64;
            uint32_t d = swz((uint32_t)(r * 64 + lc * 16));
            size_t ao = (size_t)(m0 + r) * K + k0 + lc * 8;
            size_t bo = (size_t)(nb + r) * K + k0 + lc * 8;
            CP16(so + d,         Ah + ao);
            CP16(so + 8192 + d,  Al + ao);
            CP16(so + 16384 + d, B + bo);
        }
        CP_COMMIT();
    };

    issue(0, 0);
    issue(1, 1);

    int stg = 0;
    for (int ci = 0; ci < nch; ci++) {
        if (ci + 1 < nch) { CP_WAIT1(); } else { CP_WAIT0(); }
        __syncthreads();
        if (ci + 2 < nch) {
            int ns = stg + 2; if (ns >= 3) ns -= 3;
            issue(ci + 2, ns);
        }
        const uint32_t so = sb + stg * STAGE;
#pragma unroll
        for (int kk = 0; kk < 2; kk++) {
            uint32_t ah[2][4], al_[2][4];
            {
                int ar = lane & 15;
                int akb = kk * 32 + ((lane >> 4) * 16);
#pragma unroll
                for (int i = 0; i < 2; i++) {
                    uint32_t off = swz((uint32_t)((wm * 32 + i * 16 + ar) * 64 + akb));
                    ldsm4(ah[i][0], ah[i][1], ah[i][2], ah[i][3], so + off);
                    ldsm4(al_[i][0], al_[i][1], al_[i][2], al_[i][3], so + 8192 + off);
                }
            }
            uint32_t bh[8][2];
            {
                int br = (lane & 7) + ((lane >> 4) & 1) * 8;
                int bkb = ((lane >> 3) & 1) * 16 + kk * 32;
#pragma unroll
                for (int jf = 0; jf < 4; jf++) {
                    uint32_t off = swz((uint32_t)((wn * 64 + jf * 16 + br) * 64 + bkb));
                    uint32_t r0, r1, r2, r3;
                    ldsm4(r0, r1, r2, r3, so + 16384 + off);
                    bh[2 * jf][0] = r0; bh[2 * jf][1] = r1;
                    bh[2 * jf + 1][0] = r2; bh[2 * jf + 1][1] = r3;
                }
            }
#pragma unroll
            for (int i = 0; i < 2; i++)
#pragma unroll
                for (int j = 0; j < 8; j++)
                    mma16816(acc[i][j], ah[i], bh[j]);
#pragma unroll
            for (int i = 0; i < 2; i++)
#pragma unroll
                for (int j = 0; j < 8; j++)
                    mma16816(acc[i][j], al_[i], bh[j]);
        }
        stg++; if (stg == 3) stg = 0;
    }

#pragma unroll
    for (int i = 0; i < 2; i++) {
        int row = m0 + wm * 32 + i * 16 + (lane >> 2);
#pragma unroll
        for (int j = 0; j < 8; j++) {
            int col = n0 + wn * 64 + j * 8 + (lane & 3) * 2;
            float b0 = bias[col], b1 = bias[col + 1];
            float v0 = acc[i][j][0] + b0, v1 = acc[i][j][1] + b1;
            float v2 = acc[i][j][2] + b0, v3 = acc[i][j][3] + b1;
            size_t o0 = (size_t)row * ldC + col;
            size_t o1 = (size_t)(row + 8) * ldC + col;
            uint32_t hi, lo;
            cvt_split2(v0, v1, hi, lo);
            *reinterpret_cast<uint32_t*>(Ch + o0) = hi;
            *reinterpret_cast<uint32_t*>(Cl + o0) = lo;
            cvt_split2(v2, v3, hi, lo);
            *reinterpret_cast<uint32_t*>(Ch + o1) = hi;
            *reinterpret_cast<uint32_t*>(Cl + o1) = lo;
        }
    }
}

// ======== GEMM + fused final-dot epilogue (TWOP selects A-split passes) ======
template <int NOUT, bool TWOP>
__global__ __launch_bounds__(256, 2) void gemm_dot(
    const __half* __restrict__ Ah, const __half* __restrict__ Al,
    const __half* __restrict__ B,
    const float* __restrict__ bias, const float* __restrict__ dw,
    const float* __restrict__ dbias, float* __restrict__ dout, int K)
{
    extern __shared__ __align__(1024) char smem[];
    const uint32_t sb = smem_u32(smem);
    const int tid = threadIdx.x;
    const int lane = tid & 31;
    const int wid = tid >> 5;
    const int wm = wid & 3;
    const int wn = wid >> 2;
    const int m0 = blockIdx.y * 128;
    const int n0 = blockIdx.x * 128;

    const int nch = K >> 5;
    float acc[2][8][4] = {};
    const int lr = (tid >> 2);
    const int lc = tid & 3;

    auto issue = [&](int ci, int stg) {
        const int k0 = ci << 5;
        const uint32_t so = sb + stg * STAGE;
#pragma unroll
        for (int j = 0; j < 2; j++) {
            int r = lr + j * 64;
            uint32_t d = swz((uint32_t)(r * 64 + lc * 16));
            size_t ao = (size_t)(m0 + r) * K + k0 + lc * 8;
            size_t bo = (size_t)(n0 + r) * K + k0 + lc * 8;
            CP16(so + d, Ah + ao);
            if (TWOP) CP16(so + 8192 + d, Al + ao);
            CP16(so + 16384 + d, B + bo);
        }
        CP_COMMIT();
    };

    issue(0, 0);
    if (nch > 1) issue(1, 1);

    int stg = 0;
    for (int ci = 0; ci < nch; ci++) {
        if (ci + 1 < nch) { CP_WAIT1(); } else { CP_WAIT0(); }
        __syncthreads();
        if (ci + 2 < nch) {
            int ns = stg + 2; if (ns >= 3) ns -= 3;
            issue(ci + 2, ns);
        }
        const uint32_t so = sb + stg * STAGE;
#pragma unroll
        for (int kk = 0; kk < 2; kk++) {
            uint32_t ah[2][4], al_[2][4];
            {
                int ar = lane & 15;
                int akb = kk * 32 + ((lane >> 4) * 16);
#pragma unroll
                for (int i = 0; i < 2; i++) {
                    uint32_t off = swz((uint32_t)((wm * 32 + i * 16 + ar) * 64 + akb));
                    ldsm4(ah[i][0], ah[i][1], ah[i][2], ah[i][3], so + off);
                    if (TWOP)
                        ldsm4(al_[i][0], al_[i][1], al_[i][2], al_[i][3], so + 8192 + off);
                }
            }
            uint32_t bh[8][2];
            {
                int br = (lane & 7) + ((lane >> 4) & 1) * 8;
                int bkb = ((lane >> 3) & 1) * 16 + kk * 32;
#pragma unroll
                for (int jf = 0; jf < 4; jf++) {
                    uint32_t off = swz((uint32_t)((wn * 64 + jf * 16 + br) * 64 + bkb));
                    uint32_t r0, r1, r2, r3;
                    ldsm4(r0, r1, r2, r3, so + 16384 + off);
                    bh[2 * jf][0] = r0; bh[2 * jf][1] = r1;
                    bh[2 * jf + 1][0] = r2; bh[2 * jf + 1][1] = r3;
                }
            }
#pragma unroll
            for (int i = 0; i < 2; i++)
#pragma unroll
                for (int j = 0; j < 8; j++)
                    mma16816(acc[i][j], ah[i], bh[j]);
            if (TWOP) {
#pragma unroll
                for (int i = 0; i < 2; i++)
#pragma unroll
                    for (int j = 0; j < 8; j++)
                        mma16816(acc[i][j], al_[i], bh[j]);
            }
        }
        stg++; if (stg == 3) stg = 0;
    }

    float dsum[2][2][NOUT];
#pragma unroll
    for (int i = 0; i < 2; i++)
#pragma unroll
        for (int hf = 0; hf < 2; hf++)
#pragma unroll
            for (int o = 0; o < NOUT; o++) dsum[i][hf][o] = 0.f;

#pragma unroll
    for (int i = 0; i < 2; i++) {
#pragma unroll
        for (int j = 0; j < 8; j++) {
            int col = n0 + wn * 64 + j * 8 + (lane & 3) * 2;
            float b0 = bias[col], b1 = bias[col + 1];
            float v0 = elu1(acc[i][j][0] + b0), v1 = elu1(acc[i][j][1] + b1);
            float v2 = elu1(acc[i][j][2] + b0), v3 = elu1(acc[i][j][3] + b1);
#pragma unroll
            for (int o = 0; o < NOUT; o++) {
                float w0 = dw[o * 256 + col], w1 = dw[o * 256 + col + 1];
                dsum[i][0][o] += v0 * w0 + v1 * w1;
                dsum[i][1][o] += v2 * w0 + v3 * w1;
            }
        }
    }
#pragma unroll
    for (int i = 0; i < 2; i++)
#pragma unroll
        for (int hf = 0; hf < 2; hf++)
#pragma unroll
            for (int o = 0; o < NOUT; o++) {
                float s = dsum[i][hf][o];
                s += __shfl_xor_sync(0xffffffffu, s, 1);
                s += __shfl_xor_sync(0xffffffffu, s, 2);
                dsum[i][hf][o] = s;
            }
    if ((lane & 3) == 0) {
        const bool addb = (blockIdx.x == 0 && wn == 0);
#pragma unroll
        for (int i = 0; i < 2; i++)
#pragma unroll
            for (int hf = 0; hf < 2; hf++) {
                int row = m0 + wm * 32 + i * 16 + (lane >> 2) + hf * 8;
#pragma unroll
                for (int o = 0; o < NOUT; o++) {
                    float v = dsum[i][hf][o];
                    if (addb) v += dbias[o];
                    atomicAdd(&dout[(size_t)row * NOUT + o], v);
                }
            }
    }
}

// ======== single-pass fp16 GEMM for qk ======================================
#define QSTAGE 16384
#define QSMEM (3 * QSTAGE)
__global__ __launch_bounds__(256, 2) void gemm_qk1p(
    const __half* __restrict__ Ah, const __half* __restrict__ B,
    const float* __restrict__ bias, __half* __restrict__ Cb,
    int K, int ldC)
{
    extern __shared__ __align__(1024) char smem[];
    const uint32_t sb = smem_u32(smem);
    const int tid = threadIdx.x;
    const int lane = tid & 31;
    const int wid = tid >> 5;
    const int wm = wid & 3;
    const int wn = wid >> 2;
    const int m0 = blockIdx.y * 128;
    const int n0 = blockIdx.x * 128;

    const int nch = K >> 5;
    float acc[2][8][4] = {};
    const int lr = (tid >> 2);
    const int lc = tid & 3;

    auto issue = [&](int ci, int stg) {
        const int k0 = ci << 5;
        const uint32_t so = sb + stg * QSTAGE;
#pragma unroll
        for (int j = 0; j < 2; j++) {
            int r = lr + j * 64;
            uint32_t d = swz((uint32_t)(r * 64 + lc * 16));
            CP16(so + d,        Ah + (size_t)(m0 + r) * K + k0 + lc * 8);
            CP16(so + 8192 + d, B + (size_t)(n0 + r) * K + k0 + lc * 8);
        }
        CP_COMMIT();
    };

    issue(0, 0);
    if (nch > 1) issue(1, 1);

    int stg = 0;
    for (int ci = 0; ci < nch; ci++) {
        if (ci + 1 < nch) { CP_WAIT1(); } else { CP_WAIT0(); }
        __syncthreads();
        if (ci + 2 < nch) {
            int ns = stg + 2; if (ns >= 3) ns -= 3;
            issue(ci + 2, ns);
        }
        const uint32_t so = sb + stg * QSTAGE;
#pragma unroll
        for (int kk = 0; kk < 2; kk++) {
            uint32_t ah[2][4];
            {
                int ar = lane & 15;
                int akb = kk * 32 + ((lane >> 4) * 16);
#pragma unroll
                for (int i = 0; i < 2; i++) {
                    uint32_t off = swz((uint32_t)((wm * 32 + i * 16 + ar) * 64 + akb));
                    ldsm4(ah[i][0], ah[i][1], ah[i][2], ah[i][3], so + off);
                }
            }
            uint32_t bh[8][2];
            {
                int br = (lane & 7) + ((lane >> 4) & 1) * 8;
                int bkb = ((lane >> 3) & 1) * 16 + kk * 32;
#pragma unroll
                for (int jf = 0; jf < 4; jf++) {
                    uint32_t off = swz((uint32_t)((wn * 64 + jf * 16 + br) * 64 + bkb));
                    uint32_t r0, r1, r2, r3;
                    ldsm4(r0, r1, r2, r3, so + 8192 + off);
                    bh[2 * jf][0] = r0; bh[2 * jf][1] = r1;
                    bh[2 * jf + 1][0] = r2; bh[2 * jf + 1][1] = r3;
                }
            }
#pragma unroll
            for (int i = 0; i < 2; i++)
#pragma unroll
                for (int j = 0; j < 8; j++)
                    mma16816(acc[i][j], ah[i], bh[j]);
        }
        stg++; if (stg == 3) stg = 0;
    }

#pragma unroll
    for (int i = 0; i < 2; i++) {
        int row = m0 + wm * 32 + i * 16 + (lane >> 2);
#pragma unroll
        for (int j = 0; j < 8; j++) {
            int col = n0 + wn * 64 + j * 8 + (lane & 3) * 2;
            float b0 = bias[col], b1 = bias[col + 1];
            __half2 p0 = __floats2half2_rn(acc[i][j][0] + b0, acc[i][j][1] + b1);
            __half2 p1 = __floats2half2_rn(acc[i][j][2] + b0, acc[i][j][3] + b1);
            *reinterpret_cast<__half2*>(Cb + (size_t)row * ldC + col) = p0;
            *reinterpret_cast<__half2*>(Cb + (size_t)(row + 8) * ldC + col) = p1;
        }
    }
}

// ============ fused A-build GEMM machinery (SA=40 A layout, B single) ========
#define SA 40
#define F2_AH 0
#define F2_AL 10240
#define F2_ASTAGE 20480
#define F2_BSTAGE 8192
#define F2_BOFF (2 * F2_ASTAGE)
#define F2_TOT (F2_BOFF + 3 * F2_BSTAGE)

__device__ __forceinline__ void fused_compute_chunk_1p(
    uint32_t aBase, uint32_t bBase, int lane, int wm, int wn, float acc[2][8][4])
{
#pragma unroll
    for (int kk = 0; kk < 2; kk++) {
        uint32_t ah[2][4];
        {
            int ar = lane & 15;
            int akc = ((lane >> 4) << 3) + (kk << 4);
#pragma unroll
            for (int i = 0; i < 2; i++) {
                uint32_t off = (uint32_t)((wm * 32 + i * 16 + ar) * SA + akc) * 2;
                ldsm4(ah[i][0], ah[i][1], ah[i][2], ah[i][3], aBase + F2_AH + off);
            }
        }
        uint32_t bh[8][2];
        {
            int br = (lane & 7) + ((lane >> 4) & 1) * 8;
            int bkb = ((lane >> 3) & 1) * 16 + kk * 32;
#pragma unroll
            for (int jf = 0; jf < 4; jf++) {
                uint32_t off = swz((uint32_t)((wn * 64 + jf * 16 + br) * 64 + bkb));
                uint32_t r0, r1, r2, r3;
                ldsm4(r0, r1, r2, r3, bBase + off);
                bh[2 * jf][0] = r0; bh[2 * jf][1] = r1;
                bh[2 * jf + 1][0] = r2; bh[2 * jf + 1][1] = r3;
            }
        }
#pragma unroll
        for (int i = 0; i < 2; i++)
#pragma unroll
            for (int j = 0; j < 8; j++)
                mma16816(acc[i][j], ah[i], bh[j]);
    }
}

__device__ __forceinline__ void fused_epilogue_split(
    const float* bias, __half* Ch, __half* Cl,
    int m0, int n0, int lane, int wm, int wn, float acc[2][8][4])
{
#pragma unroll
    for (int i = 0; i < 2; i++) {
        int row = m0 + wm * 32 + i * 16 + (lane >> 2);
#pragma unroll
        for (int j = 0; j < 8; j++) {
            int col = n0 + wn * 64 + j * 8 + (lane & 3) * 2;
            float b0 = bias[col], b1 = bias[col + 1];
            float v0 = elu1(acc[i][j][0] + b0), v1 = elu1(acc[i][j][1] + b1);
            float v2 = elu1(acc[i][j][2] + b0), v3 = elu1(acc[i][j][3] + b1);
            size_t o0 = (size_t)row * HIDC + col;
            size_t o1 = (size_t)(row + 8) * HIDC + col;
            uint32_t hi, lo;
            cvt_split2(v0, v1, hi, lo);
            *reinterpret_cast<uint32_t*>(Ch + o0) = hi;
            *reinterpret_cast<uint32_t*>(Cl + o0) = lo;
            cvt_split2(v2, v3, hi, lo);
            *reinterpret_cast<uint32_t*>(Ch + o1) = hi;
            *reinterpret_cast<uint32_t*>(Cl + o1) = lo;
        }
    }
}

// ======== phi1-L1 GEMM: fp32 peA rounded to single fp16 plane in-kernel ======
#define P1A_SMEM F2_TOT
__global__ __launch_bounds__(256, 2) void gemm_phi1a(
    const float* __restrict__ peA,
    const __half* __restrict__ B,
    const float* __restrict__ bias,
    __half* __restrict__ Ch, __half* __restrict__ Cl)
{
    extern __shared__ __align__(1024) char smem[];
    const uint32_t sb = smem_u32(smem);
    const int tid = threadIdx.x;
    const int lane = tid & 31;
    const int wid = tid >> 5;
    const int wm = wid & 3;
    const int wn = wid >> 2;
    const int m0 = blockIdx.y * 128;
    const int n0 = blockIdx.x * 128;
    const int nch = KPAD1 >> 5;

    float acc[2][8][4] = {};
    float4 a_r[4];
    const int blr = tid >> 2;
    const int blc = tid & 3;

    auto issueB = [&](int ci, int s3) {
        const int k0 = ci << 5;
        const uint32_t so = sb + F2_BOFF + s3 * F2_BSTAGE;
#pragma unroll
        for (int j = 0; j < 2; j++) {
            int r = blr + j * 64;
            uint32_t d = swz((uint32_t)(r * 64 + blc * 16));
            CP16(so + d, B + (size_t)(n0 + r) * KPAD1 + k0 + blc * 8);
        }
        CP_COMMIT();
    };
    auto prefA = [&](int ci) {
        const int k0 = ci << 5;
#pragma unroll
        for (int j = 0; j < 4; j++) {
            int idx = tid + j * 256;
            int r = idx >> 3, c4 = idx & 7;
            int col = k0 + c4 * 4;
            const float* p = peA + (size_t)(m0 + r) * 514 + col;
            float4 v = make_float4(0.f, 0.f, 0.f, 0.f);
            if (col + 3 < 514) {
                float2 x = *reinterpret_cast<const float2*>(p);
                float2 y = *reinterpret_cast<const float2*>(p + 2);
                v = make_float4(x.x, x.y, y.x, y.y);
            } else {
                if (col + 0 < 514) v.x = p[0];
                if (col + 1 < 514) v.y = p[1];
                if (col + 2 < 514) v.z = p[2];
                if (col + 3 < 514) v.w = p[3];
            }
            a_r[j] = v;
        }
    };

    issueB(0, 0);
    issueB(1, 1);
    prefA(0);

    int s3 = 0;
    for (int ci = 0; ci < nch; ci++) {
        const int s2 = ci & 1;
        if (ci + 1 < nch) { CP_WAIT1(); } else { CP_WAIT0(); }
        __syncthreads();
        if (ci + 2 < nch) {
            int ns = s3 + 2; if (ns >= 3) ns -= 3;
            issueB(ci + 2, ns);
        }
#pragma unroll
        for (int j = 0; j < 4; j++) {
            int idx = tid + j * 256;
            int r = idx >> 3, c4 = idx & 7;
            __half2 p01 = __floats2half2_rn(a_r[j].x, a_r[j].y);
            __half2 p23 = __floats2half2_rn(a_r[j].z, a_r[j].w);
            uint32_t o = (uint32_t)(r * SA + c4 * 4) * 2;
            *reinterpret_cast<uint2*>(smem + s2 * F2_ASTAGE + F2_AH + o) =
                make_uint2(*reinterpret_cast<uint32_t*>(&p01),
                           *reinterpret_cast<uint32_t*>(&p23));
        }
        if (ci + 1 < nch) prefA(ci + 1);
        __syncthreads();
        fused_compute_chunk_1p(sb + s2 * F2_ASTAGE, sb + F2_BOFF + s3 * F2_BSTAGE,
                               lane, wm, wn, acc);
        s3++; if (s3 == 3) s3 = 0;
    }

    fused_epilogue_split(bias, Ch, Cl, m0, n0, lane, wm, wn, acc);
}

// ======== alt2: dual-source GEMM, fully single-pass ==========================
#define ALT2_KMP 8192
#define ALT2_SMEM (ALT2_KMP + F2_TOT)
__global__ __launch_bounds__(256, 2) void gemm_alt2(
    const float* __restrict__ pe,
    const __half* __restrict__ h1h,
    const float* __restrict__ kmP,
    const __half* __restrict__ B1, const __half* __restrict__ B2,
    __half* __restrict__ Ch, __half* __restrict__ Cl)
{
    extern __shared__ __align__(1024) char smem[];
    float* kmS = reinterpret_cast<float*>(smem);
    char* sdata = smem + ALT2_KMP;
    const uint32_t sb = smem_u32(smem) + ALT2_KMP;
    const int tid = threadIdx.x;
    const int lane = tid & 31;
    const int wid = tid >> 5;
    const int wm = wid & 3;
    const int wn = wid >> 2;
    const int m0 = blockIdx.y * 128;
    const int n0 = blockIdx.x * 128;
    const int nch = 24;

    float acc[2][8][4] = {};
    uint2 a_r[4];
    const int blr = tid >> 2;
    const int blc = tid & 3;

    auto issueB = [&](int ci, int s3) {
        const uint32_t so = sb + F2_BOFF + s3 * F2_BSTAGE;
#pragma unroll
        for (int j = 0; j < 2; j++) {
            int r = blr + j * 64;
            uint32_t d = swz((uint32_t)(r * 64 + blc * 16));
            if (ci < 16)
                CP16(so + d, B1 + (size_t)(n0 + r) * 512 + (ci << 5) + blc * 8);
            else
                CP16(so + d, B2 + (size_t)(n0 + r) * 256 + ((ci - 16) << 5) + blc * 8);
        }
        CP_COMMIT();
    };
    auto prefA = [&](int ci) {
#pragma unroll
        for (int j = 0; j < 4; j++) {
            int idx = tid + j * 256;
            int r = idx >> 3, c4 = idx & 7;
            if (ci < 16) {
                size_t ao = (size_t)(m0 + r) * 512 + (ci << 5) + c4 * 4;
                float4 v = *reinterpret_cast<const float4*>(pe + ao);
                __half2 p01 = __floats2half2_rn(v.x, v.y);
                __half2 p23 = __floats2half2_rn(v.z, v.w);
                a_r[j] = make_uint2(*reinterpret_cast<uint32_t*>(&p01),
                                    *reinterpret_cast<uint32_t*>(&p23));
            } else {
                size_t ao = (size_t)(m0 + r) * 256 + ((ci - 16) << 5) + c4 * 4;
                a_r[j] = *reinterpret_cast<const uint2*>(h1h + ao);
            }
        }
    };

    const int g0 = m0 >> 4;
    for (int i = tid; i < 2048; i += 256)
        kmS[i] = kmP[(size_t)(g0 + (i >> 8)) * 256 + (i & 255)];

    issueB(0, 0);
    issueB(1, 1);
    prefA(0);

    int s3 = 0;
    for (int ci = 0; ci < nch; ci++) {
        const int s2 = ci & 1;
        if (ci + 1 < nch) { CP_WAIT1(); } else { CP_WAIT0(); }
        __syncthreads();
        if (ci + 2 < nch) {
            int ns = s3 + 2; if (ns >= 3) ns -= 3;
            issueB(ci + 2, ns);
        }
#pragma unroll
        for (int j = 0; j < 4; j++) {
            int idx = tid + j * 256;
            int r = idx >> 3, c4 = idx & 7;
            uint32_t o = (uint32_t)(r * SA + c4 * 4) * 2;
            *reinterpret_cast<uint2*>(sdata + s2 * F2_ASTAGE + F2_AH + o) = a_r[j];
        }
        if (ci + 1 < nch) prefA(ci + 1);
        __syncthreads();
        fused_compute_chunk_1p(sb + s2 * F2_ASTAGE, sb + F2_BOFF + s3 * F2_BSTAGE,
                               lane, wm, wn, acc);
        s3++; if (s3 == 3) s3 = 0;
    }

#pragma unroll
    for (int i = 0; i < 2; i++) {
        int rl = wm * 32 + i * 16 + (lane >> 2);
        int row = m0 + rl;
#pragma unroll
        for (int j = 0; j < 8; j++) {
            int col = n0 + wn * 64 + j * 8 + (lane & 3) * 2;
            float b0a = kmS[(rl >> 4) * 256 + col];
            float b1a = kmS[(rl >> 4) * 256 + col + 1];
            float b0b = kmS[((rl + 8) >> 4) * 256 + col];
            float b1b = kmS[((rl + 8) >> 4) * 256 + col + 1];
            float v0 = elu1(acc[i][j][0] + b0a), v1 = elu1(acc[i][j][1] + b1a);
            float v2 = elu1(acc[i][j][2] + b0b), v3 = elu1(acc[i][j][3] + b1b);
            size_t o0 = (size_t)row * HIDC + col;
            size_t o1 = (size_t)(row + 8) * HIDC + col;
            uint32_t hi, lo;
            cvt_split2(v0, v1, hi, lo);
            *reinterpret_cast<uint32_t*>(Ch + o0) = hi;
            *reinterpret_cast<uint32_t*>(Cl + o0) = lo;
            cvt_split2(v2, v3, hi, lo);
            *reinterpret_cast<uint32_t*>(Ch + o1) = hi;
            *reinterpret_cast<uint32_t*>(Cl + o1) = lo;
        }
    }
}

// ---------------- multi-segment weight convert ----------------
#define MAXSEG 9
struct ConvSegs {
    const float* src[MAXSEG];
    int dstoff[MAXSEG];
    int C[MAXSEG];
    int Cp[MAXSEG];
    int rows[MAXSEG];
    int n;
};
__global__ __launch_bounds__(256) void conv_multi(
    ConvSegs p, __half* __restrict__ dst)
{
    const uint32_t stride = gridDim.x * 256u;
    const uint32_t base = blockIdx.x * 256u + threadIdx.x;
    for (int s = 0; s < p.n; s++) {
        const float* src = p.src[s];
        const int C = p.C[s], Cp = p.Cp[s], off = p.dstoff[s];
        const uint32_t tot = (uint32_t)p.rows[s] * Cp;
        for (uint32_t i = base; i < tot; i += stride) {
            uint32_t r = i / (uint32_t)Cp;
            int c = (int)(i - r * (uint32_t)Cp);
            float v = (c < C) ? src[(size_t)r * C + c] : 0.f;
            dst[off + i] = __float2half(v);
        }
    }
}

// ---------------- compose all: {Wqk, Wv01, P2W1} x W4 -----------------------
__global__ __launch_bounds__(256) void compose_all(
    const float* __restrict__ wqk, const float* __restrict__ wv01,
    const float* __restrict__ p2w1, const float* __restrict__ w4,
    const float* __restrict__ b4, const float* __restrict__ battn,
    const float* __restrict__ p2b1,
    __half* __restrict__ wp,
    float* __restrict__ bc, float* __restrict__ bv2, float* __restrict__ bb)
{
    __shared__ float wrow[512];
    const int blk = blockIdx.x;
    const int tid = threadIdx.x;
    const float* src;
    const float* bin;
    float* bout;
    float scale;
    int outoff, n;
    if (blk < 1024)      { src = wqk;  n = blk;        scale = 1.f;      outoff = OW_WC;  bin = battn;        bout = bc;  }
    else if (blk < 1536) { src = wv01; n = blk - 1024; scale = 1.f;      outoff = OW_WVC; bin = battn + 1024; bout = bv2; }
    else                 { src = p2w1; n = blk - 1536; scale = -0.0625f; outoff = OW_WC3; bin = p2b1;         bout = bb;  }
    wrow[tid] = src[(size_t)n * 512 + tid];
    wrow[tid + 256] = src[(size_t)n * 512 + tid + 256];
    __syncthreads();
    float acc = 0.f;
#pragma unroll 8
    for (int j = 0; j < 512; j++)
        acc += wrow[j] * w4[(size_t)j * 256 + tid];
    wp[outoff + (size_t)n * 256 + tid] = __float2half(acc * scale);
    if (tid < 32) {
        float s = 0.f;
        for (int j = tid; j < 512; j += 32) s += wrow[j] * b4[j];
#pragma unroll
        for (int o = 16; o > 0; o >>= 1) s += __shfl_xor_sync(0xffffffffu, s, o);
        if (tid == 0) bout[n] = s * scale + bin[n];
    }
}

// ---------------- zero output ----------------
__global__ __launch_bounds__(256) void zero_out(float* __restrict__ p, int n) {
    int i = blockIdx.x * 256 + threadIdx.x;
    if (i < n) p[i] = 0.f;
}

// ---------------- attention v4: mma scores, h1-based hw ---------------------
#define AROW 1032
__global__ __launch_bounds__(256) void attn4_kernel(
    const __half* __restrict__ qk,
    const __half* __restrict__ h1h, const __half* __restrict__ h1l,
    __half* __restrict__ hwh, __half* __restrict__ hwl)
{
    const int g = blockIdx.x;
    const int tid = threadIdx.x;
    const int lane = tid & 31;
    const int wid = tid >> 5;
    __shared__ __align__(16) __half qks[16 * AROW];
    __shared__ float sc[2][16][17];
    __shared__ float cw[2][16];
    const uint32_t sbq = smem_u32(qks);

    {
        const uint4* src = reinterpret_cast<const uint4*>(qk + (size_t)g * GSZ * 1024);
#pragma unroll
        for (int t = 0; t < 8; t++) {
            int idx = tid + t * 256;
            int row = idx >> 7;
            int c8 = idx & 127;
            *reinterpret_cast<uint4*>(qks + row * AROW + c8 * 8) = src[idx];
        }
    }
    __syncthreads();

    if (wid < 2) {
        const int h = wid;
        float accS[2][4] = {};
        const uint32_t qb = (uint32_t)(h * 256) * 2;
        const uint32_t kb = (uint32_t)(512 + h * 256) * 2;
#pragma unroll
        for (int ks = 0; ks < 16; ks++) {
            uint32_t a[4];
            {
                int ar = lane & 15;
                uint32_t addr = sbq + (uint32_t)(ar * AROW) * 2 + qb + ks * 32 + (lane >> 4) * 16;
                ldsm4(a[0], a[1], a[2], a[3], addr);
            }
            uint32_t b0[2], b1[2];
            {
                int br = (lane & 7) + ((lane >> 4) & 1) * 8;
                uint32_t addr = sbq + (uint32_t)(br * AROW) * 2 + kb + ks * 32 + ((lane >> 3) & 1) * 16;
                uint32_t r0, r1, r2, r3;
                ldsm4(r0, r1, r2, r3, addr);
                b0[0] = r0; b0[1] = r1;
                b1[0] = r2; b1[1] = r3;
            }
            mma16816(accS[0], a, b0);
            mma16816(accS[1], a, b1);
        }
        {
            int row = lane >> 2;
            int col = (lane & 3) * 2;
#pragma unroll
            for (int j = 0; j < 2; j++) {
                sc[h][row][j * 8 + col]     = accS[j][0] * 0.0625f;
                sc[h][row][j * 8 + col + 1] = accS[j][1] * 0.0625f;
                sc[h][row + 8][j * 8 + col]     = accS[j][2] * 0.0625f;
                sc[h][row + 8][j * 8 + col + 1] = accS[j][3] * 0.0625f;
            }
        }
    }
    __syncthreads();

    if (tid < 32) {
        int h = tid >> 4, tq = tid & 15;
        float mx = -1e30f;
#pragma unroll
        for (int tk = 0; tk < 16; tk++) mx = fmaxf(mx, sc[h][tq][tk]);
        float s = 0.f;
#pragma unroll
        for (int tk = 0; tk < 16; tk++) {
            float e = expf(sc[h][tq][tk] - mx);
            sc[h][tq][tk] = e;
            s += e;
        }
        float inv = 1.f / s;
#pragma unroll
        for (int tk = 0; tk < 16; tk++) sc[h][tq][tk] *= inv;
    }
    __syncthreads();
    if (tid < 32) {
        int h = tid >> 4, tk = tid & 15;
        float s = 0.f;
#pragma unroll
        for (int tq = 0; tq < 16; tq++) s += sc[h][tq][tk];
        cw[h][tk] = s * 0.0625f;
    }
    __syncthreads();

    if (tid < 128) {
        int d2 = tid * 2;
        const __half* xbh = h1h + (size_t)g * GSZ * 256 + d2;
        const __half* xbl = h1l + (size_t)g * GSZ * 256 + d2;
        float a0[2] = {}, a1[2] = {};
#pragma unroll
        for (int tk = 0; tk < 16; tk++) {
            uint32_t vh = *reinterpret_cast<const uint32_t*>(xbh + tk * 256);
            uint32_t vl = *reinterpret_cast<const uint32_t*>(xbl + tk * 256);
            float2 hh = h2f2(vh), ll = h2f2(vl);
            float x0 = hh.x + ll.x, x1 = hh.y + ll.y;
            float w0 = cw[0][tk], w1 = cw[1][tk];
            a0[0] += w0 * x0; a0[1] += w0 * x1;
            a1[0] += w1 * x0; a1[1] += w1 * x1;
        }
        uint32_t hi, lo;
        size_t o0 = (size_t)g * HIDC + d2;
        cvt_split2(a0[0], a0[1], hi, lo);
        *reinterpret_cast<uint32_t*>(hwh + o0) = hi;
        *reinterpret_cast<uint32_t*>(hwl + o0) = lo;
        size_t o1 = (size_t)NGR * HIDC + o0;
        cvt_split2(a1[0], a1[1], hi, lo);
        *reinterpret_cast<uint32_t*>(hwh + o1) = hi;
        *reinterpret_cast<uint32_t*>(hwl + o1) = lo;
    }
}

// ================================================================ host launch
extern "C" void kernel_launch(void* const* d_in, const int* in_sizes, int n_in,
                              void* d_out, int out_size)
{
    const float* pe       = (const float*)d_in[0];
    const float* peA      = (const float*)d_in[1];
    const float* attn_in_w  = (const float*)d_in[2];
    const float* attn_in_b  = (const float*)d_in[3];
    const float* attn_out_w = (const float*)d_in[4];
    const float* attn_out_b = (const float*)d_in[5];
    const float* p1w1 = (const float*)d_in[6];  const float* p1b1 = (const float*)d_in[7];
    const float* p1w2 = (const float*)d_in[8];  const float* p1b2 = (const float*)d_in[9];
    const float* p1w3 = (const float*)d_in[10]; const float* p1b3 = (const float*)d_in[11];
    const float* p1w4 = (const float*)d_in[12]; const float* p1b4 = (const float*)d_in[13];
    const float* gw1 = (const float*)d_in[14];  const float* gb1 = (const float*)d_in[15];
    const float* gw2 = (const float*)d_in[16];  const float* gb2 = (const float*)d_in[17];
    const float* gw3 = (const float*)d_in[18];  const float* gb3 = (const float*)d_in[19];
    const float* gw4 = (const float*)d_in[20];  const float* gb4 = (const float*)d_in[21];
    const float* p2w1 = (const float*)d_in[22]; const float* p2b1 = (const float*)d_in[23];
    const float* p2w2 = (const float*)d_in[24]; const float* p2b2 = (const float*)d_in[25];
    const float* p2w3 = (const float*)d_in[26]; const float* p2b3 = (const float*)d_in[27];
    float* out = (float*)d_out;

    #define SYM(T, v, s) T* v; cudaGetSymbolAddress((void**)&v, s)
    SYM(__half, h1h, g_h1h);   SYM(__half, h1l, g_h1l);
    SYM(__half, h2h, g_h2h);   SYM(__half, h2l, g_h2l);
    SYM(__half, qk, g_qk);
    SYM(__half, xwh, g_xwh);   SYM(__half, xwl, g_xwl);
    SYM(__half, omh, g_omh);   SYM(__half, oml, g_oml);
    SYM(__half, kmh, g_kmh);   SYM(__half, kml, g_kml);
    SYM(float, kmpf, g_kmp);
    SYM(__half, hgah, g_hgah); SYM(__half, hgal, g_hgal);
    SYM(__half, hgbh, g_hgbh); SYM(__half, hgbl, g_hgbl);
    SYM(__half, wp, g_wp);
    SYM(float, bc, g_bc);
    SYM(float, bv2, g_bv2);
    SYM(float, bb, g_bb);

    cudaFuncSetAttribute(gemm_2p<2,2,true>,  cudaFuncAttributeMaxDynamicSharedMemorySize, SMEM_TOT);
    cudaFuncSetAttribute(gemm_2p<1,1,false>, cudaFuncAttributeMaxDynamicSharedMemorySize, SMEM_TOT);
    cudaFuncSetAttribute(gemm_2p<1,1,true>,  cudaFuncAttributeMaxDynamicSharedMemorySize, SMEM_TOT);
    cudaFuncSetAttribute(gemm_2p<0,1,true>,  cudaFuncAttributeMaxDynamicSharedMemorySize, SMEM_TOT);
    cudaFuncSetAttribute(gemm_2p<0,0,true>,  cudaFuncAttributeMaxDynamicSharedMemorySize, SMEM_TOT);
    cudaFuncSetAttribute(gemm_2p_h2, cudaFuncAttributeMaxDynamicSharedMemorySize, SMEM_TOT);
    cudaFuncSetAttribute(gemm_dot<1,true>,  cudaFuncAttributeMaxDynamicSharedMemorySize, SMEM_TOT);
    cudaFuncSetAttribute(gemm_dot<2,false>, cudaFuncAttributeMaxDynamicSharedMemorySize, SMEM_TOT);
    cudaFuncSetAttribute(gemm_qk1p, cudaFuncAttributeMaxDynamicSharedMemorySize, QSMEM);
    cudaFuncSetAttribute(gemm_phi1a, cudaFuncAttributeMaxDynamicSharedMemorySize, P1A_SMEM);
    cudaFuncSetAttribute(gemm_alt2, cudaFuncAttributeMaxDynamicSharedMemorySize, ALT2_SMEM);

    const int TB = 256;
    #define GRID(Mv, Nv) dim3((Nv) / 128, (Mv) / 128)

    // side stream + events for graph branches
    cudaStream_t s2;
    cudaStreamCreateWithFlags(&s2, cudaStreamNonBlocking);
    cudaEvent_t e0, e1, e2, e3;
    cudaEventCreateWithFlags(&e0, cudaEventDisableTiming);
    cudaEventCreateWithFlags(&e1, cudaEventDisableTiming);
    cudaEventCreateWithFlags(&e2, cudaEventDisableTiming);
    cudaEventCreateWithFlags(&e3, cudaEventDisableTiming);

    // ---- main stream: zero output ----
    zero_out<<<(out_size + 255) / 256, TB>>>(out, out_size);

    // fork A: side stream does non-phi1 weight prep
    cudaEventRecord(e0, 0);
    cudaStreamWaitEvent(s2, e0, 0);
    {
        ConvSegs s = {};
        int n = 0;
        auto add = [&](const float* src, int off, int R, int C, int Cp) {
            s.src[n] = src; s.dstoff[n] = off; s.rows[n] = R; s.C[n] = C; s.Cp[n] = Cp; n++;
        };
        add(attn_out_w, OW_WOUT, 512, 512, 512);
        add(gw1, OW_GW1, 256, 512, 512);
        add(gw2, OW_GW2, 256, 256, 256);
        add(gw3, OW_GW3, 256, 256, 256);
        add(p2w1, OW_P2W1, 256, 512, 512);
        add(p2w2, OW_P2W2, 256, 256, 256);
        s.n = n;
        conv_multi<<<512, TB, 0, s2>>>(s, wp);
    }
    compose_all<<<1792, TB, 0, s2>>>(attn_in_w, attn_in_w + (size_t)1024 * 512, p2w1,
                                     p1w4, p1b4, attn_in_b, p2b1,
                                     wp, bc, bv2, bb);
    cudaEventRecord(e1, s2);

    // ---- main: phi1 weight converts + phi1 chain ----
    {
        ConvSegs s = {};
        int n = 0;
        auto add = [&](const float* src, int off, int R, int C, int Cp) {
            s.src[n] = src; s.dstoff[n] = off; s.rows[n] = R; s.C[n] = C; s.Cp[n] = Cp; n++;
        };
        add(p1w1, OW_P1W1, 256, 514, KPAD1);
        add(p1w2, OW_P1W2, 256, 256, 256);
        add(p1w3, OW_P1W3, 256, 256, 256);
        s.n = n;
        conv_multi<<<512, TB>>>(s, wp);
    }
    gemm_phi1a<<<GRID(NTOK, 256), TB, P1A_SMEM>>>(
        peA, wp + OW_P1W1, p1b1, h1h, h1l);
    // p1w2: h1 split in -> h2 single fp16 out
    gemm_2p<2,2,true><<<GRID(NTOK, HIDC), TB, SMEM_TOT>>>(
        h1h, h1l, wp + OW_P1W2, p1b2, nullptr, h2h, nullptr, HIDC, HIDC);
    // p1w3: h2 single in (1-pass) -> h1 split out
    gemm_2p<1,1,false><<<GRID(NTOK, HIDC), TB, SMEM_TOT>>>(
        h2h, nullptr, wp + OW_P1W3, p1b3, nullptr, h1h, h1l, HIDC, HIDC);

    // join A
    cudaStreamWaitEvent(0, e1, 0);

    // qk = h1 @ Wc^T + bc (single-pass fp16, K=256)
    gemm_qk1p<<<GRID(NTOK, 1024), TB, QSMEM>>>(
        h1h, wp + OW_WC, bc, qk, HIDC, 1024);
    attn4_kernel<<<NGR, TB>>>(qk, h1h, h1l, xwh, xwl);
    gemm_2p_h2<<<GRID(NGR, 512), TB, SMEM_TOT>>>(
        xwh, xwl, xwh + (size_t)NGR * HIDC, xwl + (size_t)NGR * HIDC,
        wp + OW_WVC, wp + OW_WVC + 65536, bv2, omh, oml);
    gemm_2p<0,1,true><<<GRID(NGR, EFULL), TB, SMEM_TOT>>>(
        omh, oml, wp + OW_WOUT, attn_out_b, nullptr, kmh, kml, EFULL, EFULL);

    // fork B: g-head chain on side stream (writes out[0..NGR))
    cudaEventRecord(e2, 0);
    cudaStreamWaitEvent(s2, e2, 0);
    gemm_2p<1,1,true><<<GRID(NGR, HIDC), TB, SMEM_TOT, s2>>>(
        kmh, kml, wp + OW_GW1, gb1, nullptr, hgah, hgal, EFULL, HIDC);
    gemm_2p<1,1,true><<<GRID(NGR, HIDC), TB, SMEM_TOT, s2>>>(
        hgah, hgal, wp + OW_GW2, gb2, nullptr, hgbh, hgbl, HIDC, HIDC);
    gemm_dot<1,true><<<GRID(NGR, HIDC), TB, SMEM_TOT, s2>>>(
        hgbh, hgbl, wp + OW_GW3, gb3, gw4, gb4, out, HIDC);
    cudaEventRecord(e3, s2);

    // ---- main: alt path (writes out[NGR..)) ----
    gemm_2p<0,0,true><<<GRID(NGR, 256), TB, SMEM_TOT>>>(
        kmh, kml, wp + OW_P2W1, bb, kmpf, nullptr, nullptr, EFULL, HIDC);
    gemm_alt2<<<GRID(NTOK, 256), TB, ALT2_SMEM>>>(
        pe, h1h, kmpf, wp + OW_P2W1, wp + OW_WC3, h2h, h2l);
    gemm_dot<2,false><<<GRID(NTOK, HIDC), TB, SMEM_TOT>>>(
        h2h, h2l, wp + OW_P2W2, p2b2, p2w3, p2b3, out + NGR, HIDC);

    // join B
    cudaStreamWaitEvent(0, e3, 0);
}